// round 13
// baseline (speedup 1.0000x reference)
#include <cuda_runtime.h>
#include <cuda_fp16.h>
#include <stdint.h>
#include <math.h>

#define NP    8192
#define INC   256
#define SCC   64
#define OUTC  256
#define KPN   15
#define KDIM  (KPN * SCC)     // 960
#define AGG_PTS 16
#define KNN_TPB 128           // 32 queries/block x 4 lanes/query
#define KNN_QPB 32

// ---------------- scratch (__device__ globals, no allocations) ----------------
__device__ __align__(256) __half g_xh  [2 * NP * INC];                 // 8 MB fp16 inputs
__device__ __align__(256) float  g_h   [2 * NP * SCC];                 // 4 MB
__device__ __align__(256) int    g_idx [2 * NP * 32];                  // 2 MB
__device__ __align__(256) int    g_cnt [2 * NP];
__device__ __align__(256) __half g_agg [(size_t)2 * NP * KDIM];        // 30 MB (fp16)
__device__ __align__(256) __half g_wt1 [SCC * INC];                    // W_in^T fp16 [64][256]
__device__ __align__(256) __half g_wt  [SCC * KDIM];                   // W_kp^T fp16 [64][960]
__device__ __align__(256) __half g_wt2 [OUTC * SCC];                   // W_out^T fp16 [256][64]
__device__ __align__(256) __half g_h2  [2 * NP * SCC];                 // 2 MB fp16
__device__ __align__(256) float  g_part[2 * 2 * 64 * OUTC];
__device__ __align__(256) float  g_mu  [2 * OUTC];
__device__ __align__(256) float  g_rstd[2 * OUTC];
__device__ __align__(256) int    g_cellstart[2 * 513];
__device__ __align__(256) float4 g_sorted   [2 * NP];   // xyz + original index (bits)

// ---------------- combined grid build + fp16 conversions (one launch) ----------------
__device__ __forceinline__ int cell_of(float x, float y, float z) {
    int cx = (int)(x * 8.0f); cx = cx < 0 ? 0 : (cx > 7 ? 7 : cx);
    int cy = (int)(y * 8.0f); cy = cy < 0 ? 0 : (cy > 7 ? 7 : cy);
    int cz = (int)(z * 8.0f); cz = cz < 0 ? 0 : (cz > 7 ? 7 : cz);
    return (cz * 8 + cy) * 8 + cx;
}

#define BUILD_BLOCKS 66

__global__ __launch_bounds__(512) void grid_build(
    const float* __restrict__ c0, const float* __restrict__ c1,
    const float* __restrict__ src, const float* __restrict__ tgt,
    const float* __restrict__ Win, const float* __restrict__ Wkp,
    const float* __restrict__ Wout,
    __half* __restrict__ xh, __half* __restrict__ wt1,
    __half* __restrict__ wt, __half* __restrict__ wt2,
    int* __restrict__ start, float4* __restrict__ sorted)
{
    int b = blockIdx.x;
    int t = threadIdx.x;
    if (b < 2) {
        __shared__ short s_cell[NP];    // 16 KB
        __shared__ int s_cnt[512], s_sc[512], s_fill[512];
        const float* c = b ? c1 : c0;
        s_cnt[t] = 0; s_fill[t] = 0;
        __syncthreads();
#pragma unroll
        for (int i = 0; i < 16; i++) {
            int p = t + i * 512;
            int cell = cell_of(c[3 * p], c[3 * p + 1], c[3 * p + 2]);
            s_cell[p] = (short)cell;
            atomicAdd(&s_cnt[cell], 1);
        }
        __syncthreads();
        s_sc[t] = s_cnt[t];
        __syncthreads();
#pragma unroll
        for (int off = 1; off < 512; off <<= 1) {
            int v = (t >= off) ? s_sc[t - off] : 0;
            __syncthreads();
            s_sc[t] += v;
            __syncthreads();
        }
        start[b * 513 + t + 1] = s_sc[t];
        if (t == 0) start[b * 513] = 0;
        __syncthreads();
#pragma unroll
        for (int i = 0; i < 16; i++) {
            int p = t + i * 512;
            int cell = s_cell[p];
            int pos = s_sc[cell] - s_cnt[cell] + atomicAdd(&s_fill[cell], 1);
            sorted[b * NP + pos] = make_float4(c[3 * p], c[3 * p + 1], c[3 * p + 2],
                                               __int_as_float(p));
        }
    } else {
        int gt = (b - 2) * 512 + t;
        int stride = (BUILD_BLOCKS - 2) * 512;
        for (int i4 = gt; i4 < (2 * NP * INC) / 4; i4 += stride) {
            size_t base = (size_t)i4 * 4;
            int cl = (int)(base >> 21);
            size_t off = base & ((size_t)NP * INC - 1);
            float4 v = *reinterpret_cast<const float4*>(&(cl ? tgt : src)[off]);
            __half2 h01 = __floats2half2_rn(v.x, v.y);
            __half2 h23 = __floats2half2_rn(v.z, v.w);
            uint2 pk;
            pk.x = *reinterpret_cast<unsigned int*>(&h01);
            pk.y = *reinterpret_cast<unsigned int*>(&h23);
            *reinterpret_cast<uint2*>(&xh[base]) = pk;
        }
        for (int i = gt; i < INC * SCC; i += stride) {
            int k = i >> 6, n = i & 63;
            wt1[n * INC + k] = __float2half_rn(Win[i]);
        }
        for (int i = gt; i < KDIM * SCC; i += stride) {
            int k = i >> 6, n = i & 63;
            wt[n * KDIM + k] = __float2half_rn(Wkp[i]);
        }
        for (int i = gt; i < SCC * OUTC; i += stride) {
            int k = i >> 8, n = i & 255;
            wt2[n * SCC + k] = __float2half_rn(Wout[i]);
        }
    }
}

// ---------------- HMMA helpers ----------------
__device__ __forceinline__ void mma16816(float* c, const uint32_t* a, const uint32_t* b) {
    asm volatile(
        "mma.sync.aligned.m16n8k16.row.col.f32.f16.f16.f32 "
        "{%0,%1,%2,%3}, {%4,%5,%6,%7}, {%8,%9}, {%0,%1,%2,%3};\n"
        : "+f"(c[0]), "+f"(c[1]), "+f"(c[2]), "+f"(c[3])
        : "r"(a[0]), "r"(a[1]), "r"(a[2]), "r"(a[3]), "r"(b[0]), "r"(b[1]));
}

// ---------------- HMMA GEMM (fp32 out + bias): h = A[8192,K] @ Wt^T + b ----------------
__global__ __launch_bounds__(256) void gemm_hmma_f(
    const __half* __restrict__ A, const __half* __restrict__ Wt,
    const float* __restrict__ bias, float* __restrict__ C, int K)
{
    __shared__ __half As[128][40];
    __shared__ __half Bs[64][40];

    int cl = blockIdx.y;
    const __half* Ab = A + (size_t)cl * NP * K;
    float* Cb = C + (size_t)cl * NP * SCC;
    int row0 = blockIdx.x * 128;
    int tid = threadIdx.x, lane = tid & 31, warp = tid >> 5;
    int wm = warp >> 1, wn = warp & 1;
    int g = lane >> 2, tig = lane & 3;

    float acc[2][4][4];
#pragma unroll
    for (int am = 0; am < 2; am++)
#pragma unroll
        for (int an = 0; an < 4; an++)
#pragma unroll
            for (int d = 0; d < 4; d++) acc[am][an][d] = 0.f;

    for (int k0 = 0; k0 < K; k0 += 32) {
#pragma unroll
        for (int s = 0; s < 2; s++) {
            int ch = tid + s * 256;
            int r = ch >> 2, k8 = (ch & 3) * 8;
            *reinterpret_cast<uint4*>(&As[r][k8]) =
                *reinterpret_cast<const uint4*>(&Ab[(size_t)(row0 + r) * K + k0 + k8]);
        }
        {
            int n = tid >> 2, k8 = (tid & 3) * 8;
            *reinterpret_cast<uint4*>(&Bs[n][k8]) =
                *reinterpret_cast<const uint4*>(&Wt[(size_t)n * K + k0 + k8]);
        }
        __syncthreads();

#pragma unroll
        for (int ks = 0; ks < 32; ks += 16) {
            uint32_t a[2][4], b[4][2];
#pragma unroll
            for (int am = 0; am < 2; am++) {
                int r = wm * 32 + am * 16 + g;
                a[am][0] = *reinterpret_cast<const uint32_t*>(&As[r][ks + tig * 2]);
                a[am][1] = *reinterpret_cast<const uint32_t*>(&As[r + 8][ks + tig * 2]);
                a[am][2] = *reinterpret_cast<const uint32_t*>(&As[r][ks + tig * 2 + 8]);
                a[am][3] = *reinterpret_cast<const uint32_t*>(&As[r + 8][ks + tig * 2 + 8]);
            }
#pragma unroll
            for (int an = 0; an < 4; an++) {
                int n = wn * 32 + an * 8 + g;
                b[an][0] = *reinterpret_cast<const uint32_t*>(&Bs[n][ks + tig * 2]);
                b[an][1] = *reinterpret_cast<const uint32_t*>(&Bs[n][ks + tig * 2 + 8]);
            }
#pragma unroll
            for (int am = 0; am < 2; am++)
#pragma unroll
                for (int an = 0; an < 4; an++)
                    mma16816(acc[am][an], a[am], b[an]);
        }
        __syncthreads();
    }

#pragma unroll
    for (int am = 0; am < 2; am++)
#pragma unroll
        for (int an = 0; an < 4; an++) {
            int r = row0 + wm * 32 + am * 16 + g;
            int c = wn * 32 + an * 8 + tig * 2;
            float bv0 = bias[c], bv1 = bias[c + 1];
            float2 v0; v0.x = acc[am][an][0] + bv0; v0.y = acc[am][an][1] + bv1;
            float2 v1; v1.x = acc[am][an][2] + bv0; v1.y = acc[am][an][3] + bv1;
            *reinterpret_cast<float2*>(&Cb[(size_t)r * SCC + c]) = v0;
            *reinterpret_cast<float2*>(&Cb[(size_t)(r + 8) * SCC + c]) = v1;
        }
}

// ---------------- kNN: sorted order, 4 lanes per query (R11 version) ----------------
__global__ __launch_bounds__(KNN_TPB) void knn_grid(
    const int* __restrict__ start, const float4* __restrict__ sorted,
    int* __restrict__ out_idx, int* __restrict__ out_cnt)
{
    extern __shared__ char smraw[];
    float* smd = (float*)smraw;                          // [128][33]
    int*   smi = (int*)(smraw + KNN_TPB * 33 * 4);       // [128][33]
    int*   s_keep = (int*)(smraw + KNN_TPB * 33 * 8);    // [128]

    int cl = blockIdx.y;
    int tid = threadIdx.x;
    int lq = tid & 3;
    int quad = tid >> 2;
    int s = blockIdx.x * KNN_QPB + quad;

    const int* st = start + cl * 513;
    const float4* srt = sorted + (size_t)cl * NP;

    float4 q4 = srt[s];
    float qx = q4.x, qy = q4.y, qz = q4.z;
    int orig = __float_as_int(q4.w);
    const float R2 = 0.0144f;

    int cx = (int)(qx * 8.0f); cx = cx < 0 ? 0 : (cx > 7 ? 7 : cx);
    int cy = (int)(qy * 8.0f); cy = cy < 0 ? 0 : (cy > 7 ? 7 : cy);
    int cz = (int)(qz * 8.0f); cz = cz < 0 ? 0 : (cz > 7 ? 7 : cz);
    int xlo = cx > 0 ? cx - 1 : 0, xhi = cx < 7 ? cx + 1 : 7;
    int ylo = cy > 0 ? cy - 1 : 0, yhi = cy < 7 ? cy + 1 : 7;
    int zlo = cz > 0 ? cz - 1 : 0, zhi = cz < 7 ? cz + 1 : 7;

    float* md = smd + tid * 33;
    int*   mi = smi + tid * 33;
    int keep = 0;
    float cm = 0.f; int ca = 0;

    for (int z = zlo; z <= zhi; z++)
        for (int y = ylo; y <= yhi; y++) {
            int rowcell = (z * 8 + y) * 8;
            int jb = st[rowcell + xlo];
            int je = st[rowcell + xhi + 1];
#pragma unroll 2
            for (int j = jb + lq; j < je; j += 4) {
                float4 pc = srt[j];
                float dx = __fsub_rn(qx, pc.x);
                float dy = __fsub_rn(qy, pc.y);
                float dz = __fsub_rn(qz, pc.z);
                float d2 = __fadd_rn(__fadd_rn(__fmul_rn(dx, dx), __fmul_rn(dy, dy)),
                                     __fmul_rn(dz, dz));
                if (d2 <= R2) {
                    if (keep < 32) {
                        md[keep] = d2; mi[keep] = __float_as_int(pc.w); keep++;
                        if (keep == 32) {
                            cm = md[0]; ca = 0;
#pragma unroll
                            for (int u = 1; u < 32; u++) { float v = md[u]; if (v > cm) { cm = v; ca = u; } }
                        }
                    } else if (d2 < cm) {
                        md[ca] = d2; mi[ca] = __float_as_int(pc.w);
                        cm = md[0]; ca = 0;
#pragma unroll
                        for (int u = 1; u < 32; u++) { float v = md[u]; if (v > cm) { cm = v; ca = u; } }
                    }
                }
            }
        }

    s_keep[tid] = keep;
    __syncwarp();

    if (lq == 0) {
        for (int l = 1; l < 4; l++) {
            const float* od = smd + (tid + l) * 33;
            const int*   oi2 = smi + (tid + l) * 33;
            int oc = s_keep[tid + l];
            for (int e = 0; e < oc; e++) {
                float d2 = od[e];
                int ix = oi2[e];
                if (keep < 32) {
                    md[keep] = d2; mi[keep] = ix; keep++;
                    if (keep == 32) {
                        cm = md[0]; ca = 0;
#pragma unroll
                        for (int u = 1; u < 32; u++) { float v = md[u]; if (v > cm) { cm = v; ca = u; } }
                    }
                } else if (d2 < cm) {
                    md[ca] = d2; mi[ca] = ix;
                    cm = md[0]; ca = 0;
#pragma unroll
                    for (int u = 1; u < 32; u++) { float v = md[u]; if (v > cm) { cm = v; ca = u; } }
                }
            }
        }
        int* oi = out_idx + ((size_t)cl * NP + orig) * 32;
        for (int u = 0; u < 32; u++) oi[u] = (u < keep) ? mi[u] : 0;
        out_cnt[cl * NP + orig] = keep;
    }
}

// ---------------- KPConv aggregate: 512 threads, warp per point, p-split ----------------
// One warp handles one point. Lanes 0-15 accumulate kernel-points 0-7, lanes
// 16-31 accumulate 8-14 (8th slot padded with zero weight). 32 regs of acc per
// thread -> ~2x occupancy vs the 15-acc version; kernel is FMA-pipe bound.
__global__ __launch_bounds__(512) void agg_kernel(
    const float* __restrict__ c0, const float* __restrict__ c1,
    const int* __restrict__ idx, const int* __restrict__ cntArr,
    const float* __restrict__ h, const float* __restrict__ kpts,
    __half* __restrict__ agg)
{
    __shared__ __align__(16) float s_infl[AGG_PTS][32][16];   // padded, float4 loads
    __shared__ int   s_idx[AGG_PTS][32];
    __shared__ float s_rel[AGG_PTS][32][3];
    __shared__ float s_kp[KPN][3];
    __shared__ int   s_cnt[AGG_PTS];

    int cl = blockIdx.y;
    const float* coords = cl ? c1 : c0;
    int p0 = blockIdx.x * AGG_PTS;
    int tid = threadIdx.x;
    size_t qbase = (size_t)cl * NP + p0;

    if (tid < KPN * 3) s_kp[tid / 3][tid % 3] = kpts[tid];
    if (tid < AGG_PTS) s_cnt[tid] = cntArr[qbase + tid];
    {
        int pt = tid >> 5, k = tid & 31;
        s_idx[pt][k] = idx[(qbase + pt) * 32 + k];
    }
    __syncthreads();

    {
        int pt = tid >> 5, k = tid & 31;
        int j = s_idx[pt][k], n = p0 + pt;
        s_rel[pt][k][0] = __fsub_rn(coords[3 * j],     coords[3 * n]);
        s_rel[pt][k][1] = __fsub_rn(coords[3 * j + 1], coords[3 * n + 1]);
        s_rel[pt][k][2] = __fsub_rn(coords[3 * j + 2], coords[3 * n + 2]);
    }
    __syncthreads();

    {
        int pt = tid >> 5, k = tid & 31;
        float rx = s_rel[pt][k][0], ry = s_rel[pt][k][1], rz = s_rel[pt][k][2];
        bool valid = k < s_cnt[pt];
#pragma unroll
        for (int p = 0; p < KPN; p++) {
            float dx = rx - s_kp[p][0];
            float dy = ry - s_kp[p][1];
            float dz = rz - s_kp[p][2];
            float dist = sqrtf(dx * dx + dy * dy + dz * dz);
            float w = fmaxf(1.0f - dist * (1.0f / 0.096f), 0.0f);
            s_infl[pt][k][p] = valid ? w : 0.0f;
        }
        s_infl[pt][k][15] = 0.0f;
    }
    __syncthreads();

    int pt = tid >> 5;                 // warp id = point
    int half = (tid >> 4) & 1;         // 0: p 0-7, 1: p 8-15(pad)
    int c4 = (tid & 15) << 2;
    const float* hcl = h + (size_t)cl * NP * SCC;

    float acc[8][4];
#pragma unroll
    for (int p = 0; p < 8; p++)
#pragma unroll
        for (int d = 0; d < 4; d++) acc[p][d] = 0.f;

    float4 hv = *reinterpret_cast<const float4*>(&hcl[(size_t)s_idx[pt][0] * SCC + c4]);
#pragma unroll
    for (int k = 0; k < 32; k++) {
        float4 nxt;
        if (k < 31)
            nxt = *reinterpret_cast<const float4*>(&hcl[(size_t)s_idx[pt][k + 1] * SCC + c4]);
        const float4* wf = reinterpret_cast<const float4*>(&s_infl[pt][k][0]) + half * 2;
        float4 w0 = wf[0], w1 = wf[1];
        acc[0][0] += w0.x * hv.x; acc[0][1] += w0.x * hv.y; acc[0][2] += w0.x * hv.z; acc[0][3] += w0.x * hv.w;
        acc[1][0] += w0.y * hv.x; acc[1][1] += w0.y * hv.y; acc[1][2] += w0.y * hv.z; acc[1][3] += w0.y * hv.w;
        acc[2][0] += w0.z * hv.x; acc[2][1] += w0.z * hv.y; acc[2][2] += w0.z * hv.z; acc[2][3] += w0.z * hv.w;
        acc[3][0] += w0.w * hv.x; acc[3][1] += w0.w * hv.y; acc[3][2] += w0.w * hv.z; acc[3][3] += w0.w * hv.w;
        acc[4][0] += w1.x * hv.x; acc[4][1] += w1.x * hv.y; acc[4][2] += w1.x * hv.z; acc[4][3] += w1.x * hv.w;
        acc[5][0] += w1.y * hv.x; acc[5][1] += w1.y * hv.y; acc[5][2] += w1.y * hv.z; acc[5][3] += w1.y * hv.w;
        acc[6][0] += w1.z * hv.x; acc[6][1] += w1.z * hv.y; acc[6][2] += w1.z * hv.z; acc[6][3] += w1.z * hv.w;
        acc[7][0] += w1.w * hv.x; acc[7][1] += w1.w * hv.y; acc[7][2] += w1.w * hv.z; acc[7][3] += w1.w * hv.w;
        hv = nxt;
    }

    __half* o = agg + (qbase + pt) * KDIM + half * 8 * SCC + c4;
    int pmax = half ? 7 : 8;           // p=15 doesn't exist
    for (int p = 0; p < pmax; p++) {
        __half2 h01 = __floats2half2_rn(acc[p][0], acc[p][1]);
        __half2 h23 = __floats2half2_rn(acc[p][2], acc[p][3]);
        uint2 pk;
        pk.x = *reinterpret_cast<unsigned int*>(&h01);
        pk.y = *reinterpret_cast<unsigned int*>(&h23);
        *reinterpret_cast<uint2*>(&o[p * SCC]) = pk;
    }
}

// ---------------- HMMA GEMM 1: h2(fp16) = agg[8192,960] @ Wkp[960,64] ----------------
__global__ __launch_bounds__(256) void gemm_hmma(
    const __half* __restrict__ A, const __half* __restrict__ Wt,
    __half* __restrict__ C)
{
    __shared__ __half As[128][40];
    __shared__ __half Bs[64][40];

    int cl = blockIdx.y;
    const __half* Ab = A + (size_t)cl * NP * KDIM;
    __half* Cb = C + (size_t)cl * NP * SCC;
    int row0 = blockIdx.x * 128;
    int tid = threadIdx.x, lane = tid & 31, warp = tid >> 5;
    int wm = warp >> 1, wn = warp & 1;
    int g = lane >> 2, tig = lane & 3;

    float acc[2][4][4];
#pragma unroll
    for (int am = 0; am < 2; am++)
#pragma unroll
        for (int an = 0; an < 4; an++)
#pragma unroll
            for (int d = 0; d < 4; d++) acc[am][an][d] = 0.f;

    for (int k0 = 0; k0 < KDIM; k0 += 32) {
#pragma unroll
        for (int s = 0; s < 2; s++) {
            int ch = tid + s * 256;
            int r = ch >> 2, k8 = (ch & 3) * 8;
            *reinterpret_cast<uint4*>(&As[r][k8]) =
                *reinterpret_cast<const uint4*>(&Ab[(size_t)(row0 + r) * KDIM + k0 + k8]);
        }
        {
            int n = tid >> 2, k8 = (tid & 3) * 8;
            *reinterpret_cast<uint4*>(&Bs[n][k8]) =
                *reinterpret_cast<const uint4*>(&Wt[(size_t)n * KDIM + k0 + k8]);
        }
        __syncthreads();

#pragma unroll
        for (int ks = 0; ks < 32; ks += 16) {
            uint32_t a[2][4], b[4][2];
#pragma unroll
            for (int am = 0; am < 2; am++) {
                int r = wm * 32 + am * 16 + g;
                a[am][0] = *reinterpret_cast<const uint32_t*>(&As[r][ks + tig * 2]);
                a[am][1] = *reinterpret_cast<const uint32_t*>(&As[r + 8][ks + tig * 2]);
                a[am][2] = *reinterpret_cast<const uint32_t*>(&As[r][ks + tig * 2 + 8]);
                a[am][3] = *reinterpret_cast<const uint32_t*>(&As[r + 8][ks + tig * 2 + 8]);
            }
#pragma unroll
            for (int an = 0; an < 4; an++) {
                int n = wn * 32 + an * 8 + g;
                b[an][0] = *reinterpret_cast<const uint32_t*>(&Bs[n][ks + tig * 2]);
                b[an][1] = *reinterpret_cast<const uint32_t*>(&Bs[n][ks + tig * 2 + 8]);
            }
#pragma unroll
            for (int am = 0; am < 2; am++)
#pragma unroll
                for (int an = 0; an < 4; an++)
                    mma16816(acc[am][an], a[am], b[an]);
        }
        __syncthreads();
    }

#pragma unroll
    for (int am = 0; am < 2; am++)
#pragma unroll
        for (int an = 0; an < 4; an++) {
            int r = row0 + wm * 32 + am * 16 + g;
            int c = wn * 32 + an * 8 + tig * 2;
            __half2 v0 = __floats2half2_rn(acc[am][an][0], acc[am][an][1]);
            __half2 v1 = __floats2half2_rn(acc[am][an][2], acc[am][an][3]);
            *reinterpret_cast<__half2*>(&Cb[(size_t)r * SCC + c]) = v0;
            *reinterpret_cast<__half2*>(&Cb[(size_t)(r + 8) * SCC + c]) = v1;
        }
}

// ---------------- HMMA GEMM 2: y = h2[8192,64] @ W_out[64,256] + b + BN partials ----------------
__global__ __launch_bounds__(256) void gemm_hmma2(
    const __half* __restrict__ A, const __half* __restrict__ Wt2,
    const float* __restrict__ bias, float* __restrict__ C,
    float* __restrict__ part)
{
    __shared__ __half As[128][72];
    __shared__ __half Bs[128][72];
    __shared__ float s_red[2][4][128];

    int cl = blockIdx.z;
    const __half* Ab = A + (size_t)cl * NP * SCC;
    float* Cb = C + (size_t)cl * NP * OUTC;
    int row0 = blockIdx.x * 128;
    int col0 = blockIdx.y * 128;
    int tid = threadIdx.x, lane = tid & 31, warp = tid >> 5;
    int wm = warp >> 1, wn = warp & 1;
    int g = lane >> 2, tig = lane & 3;

#pragma unroll
    for (int s = 0; s < 4; s++) {
        int ch = tid + s * 256;
        int r = ch >> 3, k8 = (ch & 7) * 8;
        *reinterpret_cast<uint4*>(&As[r][k8]) =
            *reinterpret_cast<const uint4*>(&Ab[(size_t)(row0 + r) * SCC + k8]);
        *reinterpret_cast<uint4*>(&Bs[r][k8]) =
            *reinterpret_cast<const uint4*>(&Wt2[(size_t)(col0 + r) * SCC + k8]);
    }
    __syncthreads();

    float acc[2][8][4];
#pragma unroll
    for (int am = 0; am < 2; am++)
#pragma unroll
        for (int an = 0; an < 8; an++)
#pragma unroll
            for (int d = 0; d < 4; d++) acc[am][an][d] = 0.f;

#pragma unroll
    for (int ks = 0; ks < 64; ks += 16) {
        uint32_t a[2][4], b[8][2];
#pragma unroll
        for (int am = 0; am < 2; am++) {
            int r = wm * 32 + am * 16 + g;
            a[am][0] = *reinterpret_cast<const uint32_t*>(&As[r][ks + tig * 2]);
            a[am][1] = *reinterpret_cast<const uint32_t*>(&As[r + 8][ks + tig * 2]);
            a[am][2] = *reinterpret_cast<const uint32_t*>(&As[r][ks + tig * 2 + 8]);
            a[am][3] = *reinterpret_cast<const uint32_t*>(&As[r + 8][ks + tig * 2 + 8]);
        }
#pragma unroll
        for (int an = 0; an < 8; an++) {
            int n = wn * 64 + an * 8 + g;
            b[an][0] = *reinterpret_cast<const uint32_t*>(&Bs[n][ks + tig * 2]);
            b[an][1] = *reinterpret_cast<const uint32_t*>(&Bs[n][ks + tig * 2 + 8]);
        }
#pragma unroll
        for (int am = 0; am < 2; am++)
#pragma unroll
            for (int an = 0; an < 8; an++)
                mma16816(acc[am][an], a[am], b[an]);
    }

#pragma unroll
    for (int an = 0; an < 8; an++) {
        int c = wn * 64 + an * 8 + tig * 2;
        float bv0 = bias[col0 + c], bv1 = bias[col0 + c + 1];
        float s0 = 0.f, s1 = 0.f, q0 = 0.f, q1 = 0.f;
#pragma unroll
        for (int am = 0; am < 2; am++) {
            int r = row0 + wm * 32 + am * 16 + g;
            float v0 = acc[am][an][0] + bv0, v1 = acc[am][an][1] + bv1;
            float v2 = acc[am][an][2] + bv0, v3 = acc[am][an][3] + bv1;
            float2 w0; w0.x = v0; w0.y = v1;
            float2 w1; w1.x = v2; w1.y = v3;
            *reinterpret_cast<float2*>(&Cb[(size_t)r * OUTC + col0 + c]) = w0;
            *reinterpret_cast<float2*>(&Cb[(size_t)(r + 8) * OUTC + col0 + c]) = w1;
            s0 += v0 + v2; s1 += v1 + v3;
            q0 += v0 * v0 + v2 * v2; q1 += v1 * v1 + v3 * v3;
        }
#pragma unroll
        for (int m = 4; m <= 16; m <<= 1) {
            s0 += __shfl_xor_sync(0xffffffffu, s0, m);
            s1 += __shfl_xor_sync(0xffffffffu, s1, m);
            q0 += __shfl_xor_sync(0xffffffffu, q0, m);
            q1 += __shfl_xor_sync(0xffffffffu, q1, m);
        }
        if (g == 0) {
            s_red[0][wm][c] = s0; s_red[0][wm][c + 1] = s1;
            s_red[1][wm][c] = q0; s_red[1][wm][c + 1] = q1;
        }
    }
    __syncthreads();
    {
        int c = tid & 127, s = tid >> 7;
        float v = s_red[s][0][c] + s_red[s][1][c] + s_red[s][2][c] + s_red[s][3][c];
        part[((size_t)(cl * 2 + s) * 64 + blockIdx.x) * OUTC + col0 + c] = v;
    }
}

// ---------------- batch norm finalize + apply ----------------
__global__ __launch_bounds__(256) void bn_final(const float* __restrict__ part,
                                                float* __restrict__ mu,
                                                float* __restrict__ rstd)
{
    int cl = blockIdx.x, ch = threadIdx.x;
    float s = 0.f, s2 = 0.f;
    for (int r = 0; r < 64; r++) {
        s  += part[((size_t)(cl * 2 + 0) * 64 + r) * OUTC + ch];
        s2 += part[((size_t)(cl * 2 + 1) * 64 + r) * OUTC + ch];
    }
    float m = s * (1.0f / 8192.0f);
    float v = s2 * (1.0f / 8192.0f) - m * m;
    v = v < 0.f ? 0.f : v;
    mu[cl * OUTC + ch]   = m;
    rstd[cl * OUTC + ch] = rsqrtf(v + 1e-5f);
}

__global__ __launch_bounds__(256) void bn_apply(float* __restrict__ y,
                                                const float* __restrict__ mu,
                                                const float* __restrict__ rstd,
                                                const float* __restrict__ gamma,
                                                const float* __restrict__ beta)
{
    size_t i4 = (size_t)blockIdx.x * blockDim.x + threadIdx.x;
    size_t base = i4 * 4;
    int ch = (int)(base & (OUTC - 1));
    int cl = (int)(base >> 21);
    float4 v = *reinterpret_cast<float4*>(&y[base]);
    const float* muc = mu + cl * OUTC + ch;
    const float* rsc = rstd + cl * OUTC + ch;
    const float* gc = gamma + ch;
    const float* bc = beta + ch;
    float t0 = gc[0] * (v.x - muc[0]) * rsc[0] + bc[0];
    float t1 = gc[1] * (v.y - muc[1]) * rsc[1] + bc[1];
    float t2 = gc[2] * (v.z - muc[2]) * rsc[2] + bc[2];
    float t3 = gc[3] * (v.w - muc[3]) * rsc[3] + bc[3];
    v.x = t0 > 0.f ? t0 : 0.1f * t0;
    v.y = t1 > 0.f ? t1 : 0.1f * t1;
    v.z = t2 > 0.f ? t2 : 0.1f * t2;
    v.w = t3 > 0.f ? t3 : 0.1f * t3;
    *reinterpret_cast<float4*>(&y[base]) = v;
}

// ---------------- launch ----------------
extern "C" void kernel_launch(void* const* d_in, const int* in_sizes, int n_in,
                              void* d_out, int out_size)
{
    const float* src    = (const float*)d_in[0];
    const float* tgt    = (const float*)d_in[1];
    const float* src_c  = (const float*)d_in[2];
    const float* tgt_c  = (const float*)d_in[3];
    const float* W_in   = (const float*)d_in[4];
    const float* b_in   = (const float*)d_in[5];
    const float* kpts   = (const float*)d_in[6];
    const float* W_kp   = (const float*)d_in[7];
    const float* W_out  = (const float*)d_in[8];
    const float* b_out  = (const float*)d_in[9];
    const float* gamma  = (const float*)d_in[10];
    const float* beta   = (const float*)d_in[11];
    float* out = (float*)d_out;

    void* p;
    cudaGetSymbolAddress(&p, g_xh);       __half* xhP   = (__half*)p;
    cudaGetSymbolAddress(&p, g_h);        float*  hP    = (float*)p;
    cudaGetSymbolAddress(&p, g_idx);      int*    idxP  = (int*)p;
    cudaGetSymbolAddress(&p, g_cnt);      int*    cntP  = (int*)p;
    cudaGetSymbolAddress(&p, g_agg);      __half* aggP  = (__half*)p;
    cudaGetSymbolAddress(&p, g_wt1);      __half* wt1P  = (__half*)p;
    cudaGetSymbolAddress(&p, g_wt);       __half* wtP   = (__half*)p;
    cudaGetSymbolAddress(&p, g_wt2);      __half* wt2P  = (__half*)p;
    cudaGetSymbolAddress(&p, g_h2);       __half* h2P   = (__half*)p;
    cudaGetSymbolAddress(&p, g_part);     float*  partP = (float*)p;
    cudaGetSymbolAddress(&p, g_mu);       float*  muP   = (float*)p;
    cudaGetSymbolAddress(&p, g_rstd);     float*  rstdP = (float*)p;
    cudaGetSymbolAddress(&p, g_cellstart);int*    cstP  = (int*)p;
    cudaGetSymbolAddress(&p, g_sorted);   float4* srtP  = (float4*)p;

    const int KNN_SMEM = KNN_TPB * 33 * 8 + KNN_TPB * 4;   // 34304 B
    cudaFuncSetAttribute(knn_grid, cudaFuncAttributeMaxDynamicSharedMemorySize, KNN_SMEM);

    // 0) grid build + all fp16 conversions (single launch)
    grid_build<<<BUILD_BLOCKS, 512>>>(src_c, tgt_c, src, tgt, W_in, W_kp, W_out,
                                      xhP, wt1P, wtP, wt2P, cstP, srtP);

    // 1) h = x @ W_in + b_in  (HMMA, fp32 out)
    gemm_hmma_f<<<dim3(NP / 128, 2), 256>>>(xhP, wt1P, b_in, hP, INC);

    // 2) grid kNN: sorted order, 4 lanes per query
    knn_grid<<<dim3(NP / KNN_QPB, 2), KNN_TPB, KNN_SMEM>>>(cstP, srtP, idxP, cntP);

    // 3) KPConv influence-weighted aggregation -> agg [N, 960] (fp16)
    agg_kernel<<<dim3(NP / AGG_PTS, 2), 512>>>(src_c, tgt_c, idxP, cntP, hP, kpts, aggP);

    // 4) h2(fp16) = agg @ W_kp  (HMMA)
    gemm_hmma<<<dim3(NP / 128, 2), 256>>>(aggP, wtP, h2P);

    // 5) y = h2 @ W_out + b_out -> d_out (HMMA) with fused BN partials
    gemm_hmma2<<<dim3(NP / 128, 2, 2), 256>>>(h2P, wt2P, b_out, out, partP);

    // 6) batch norm finalize + apply (in place on d_out)
    bn_final<<<2, 256>>>(partP, muP, rstdP);
    bn_apply<<<(2 * NP * OUTC / 4) / 256, 256>>>(out, muP, rstdP, gamma, beta);

    // 7) coords pass-through
    cudaMemcpyAsync(out + (size_t)2 * NP * OUTC, src_c, NP * 3 * sizeof(float),
                    cudaMemcpyDeviceToDevice);
    cudaMemcpyAsync(out + (size_t)2 * NP * OUTC + NP * 3, tgt_c, NP * 3 * sizeof(float),
                    cudaMemcpyDeviceToDevice);
}

// round 14
// speedup vs baseline: 1.0929x; 1.0929x over previous
#include <cuda_runtime.h>
#include <cuda_fp16.h>
#include <stdint.h>
#include <math.h>

#define NP    8192
#define INC   256
#define SCC   64
#define OUTC  256
#define KPN   15
#define KDIM  (KPN * SCC)     // 960
#define AGG_PTS 16
#define KNN_TPB 128           // 32 queries/block x 4 lanes/query
#define KNN_QPB 32

// ---------------- scratch (__device__ globals, no allocations) ----------------
__device__ __align__(256) __half g_xh  [2 * NP * INC];                 // 8 MB fp16 inputs
__device__ __align__(256) float  g_h   [2 * NP * SCC];                 // 4 MB
__device__ __align__(256) int    g_idx [2 * NP * 32];                  // 2 MB
__device__ __align__(256) int    g_cnt [2 * NP];
__device__ __align__(256) __half g_agg [(size_t)2 * NP * KDIM];        // 30 MB (fp16)
__device__ __align__(256) __half g_wt1 [SCC * INC];                    // W_in^T fp16 [64][256]
__device__ __align__(256) __half g_wt  [SCC * KDIM];                   // W_kp^T fp16 [64][960]
__device__ __align__(256) __half g_wt2 [OUTC * SCC];                   // W_out^T fp16 [256][64]
__device__ __align__(256) __half g_h2  [2 * NP * SCC];                 // 2 MB fp16
__device__ __align__(256) float  g_part[2 * 2 * 64 * OUTC];
__device__ __align__(256) float  g_mu  [2 * OUTC];
__device__ __align__(256) float  g_rstd[2 * OUTC];
__device__ __align__(256) int    g_cellstart[2 * 513];
__device__ __align__(256) float4 g_sorted   [2 * NP];   // xyz + original index (bits)

// ---------------- combined grid build + fp16 conversions (one launch) ----------------
__device__ __forceinline__ int cell_of(float x, float y, float z) {
    int cx = (int)(x * 8.0f); cx = cx < 0 ? 0 : (cx > 7 ? 7 : cx);
    int cy = (int)(y * 8.0f); cy = cy < 0 ? 0 : (cy > 7 ? 7 : cy);
    int cz = (int)(z * 8.0f); cz = cz < 0 ? 0 : (cz > 7 ? 7 : cz);
    return (cz * 8 + cy) * 8 + cx;
}

#define BUILD_BLOCKS 66

__global__ __launch_bounds__(512) void grid_build(
    const float* __restrict__ c0, const float* __restrict__ c1,
    const float* __restrict__ src, const float* __restrict__ tgt,
    const float* __restrict__ Win, const float* __restrict__ Wkp,
    const float* __restrict__ Wout,
    __half* __restrict__ xh, __half* __restrict__ wt1,
    __half* __restrict__ wt, __half* __restrict__ wt2,
    int* __restrict__ start, float4* __restrict__ sorted)
{
    int b = blockIdx.x;
    int t = threadIdx.x;
    if (b < 2) {
        __shared__ short s_cell[NP];    // 16 KB
        __shared__ int s_cnt[512], s_sc[512], s_fill[512];
        const float* c = b ? c1 : c0;
        s_cnt[t] = 0; s_fill[t] = 0;
        __syncthreads();
#pragma unroll
        for (int i = 0; i < 16; i++) {
            int p = t + i * 512;
            int cell = cell_of(c[3 * p], c[3 * p + 1], c[3 * p + 2]);
            s_cell[p] = (short)cell;
            atomicAdd(&s_cnt[cell], 1);
        }
        __syncthreads();
        s_sc[t] = s_cnt[t];
        __syncthreads();
#pragma unroll
        for (int off = 1; off < 512; off <<= 1) {
            int v = (t >= off) ? s_sc[t - off] : 0;
            __syncthreads();
            s_sc[t] += v;
            __syncthreads();
        }
        start[b * 513 + t + 1] = s_sc[t];
        if (t == 0) start[b * 513] = 0;
        __syncthreads();
#pragma unroll
        for (int i = 0; i < 16; i++) {
            int p = t + i * 512;
            int cell = s_cell[p];
            int pos = s_sc[cell] - s_cnt[cell] + atomicAdd(&s_fill[cell], 1);
            sorted[b * NP + pos] = make_float4(c[3 * p], c[3 * p + 1], c[3 * p + 2],
                                               __int_as_float(p));
        }
    } else {
        int gt = (b - 2) * 512 + t;
        int stride = (BUILD_BLOCKS - 2) * 512;
        for (int i4 = gt; i4 < (2 * NP * INC) / 4; i4 += stride) {
            size_t base = (size_t)i4 * 4;
            int cl = (int)(base >> 21);
            size_t off = base & ((size_t)NP * INC - 1);
            float4 v = *reinterpret_cast<const float4*>(&(cl ? tgt : src)[off]);
            __half2 h01 = __floats2half2_rn(v.x, v.y);
            __half2 h23 = __floats2half2_rn(v.z, v.w);
            uint2 pk;
            pk.x = *reinterpret_cast<unsigned int*>(&h01);
            pk.y = *reinterpret_cast<unsigned int*>(&h23);
            *reinterpret_cast<uint2*>(&xh[base]) = pk;
        }
        for (int i = gt; i < INC * SCC; i += stride) {
            int k = i >> 6, n = i & 63;
            wt1[n * INC + k] = __float2half_rn(Win[i]);
        }
        for (int i = gt; i < KDIM * SCC; i += stride) {
            int k = i >> 6, n = i & 63;
            wt[n * KDIM + k] = __float2half_rn(Wkp[i]);
        }
        for (int i = gt; i < SCC * OUTC; i += stride) {
            int k = i >> 8, n = i & 255;
            wt2[n * SCC + k] = __float2half_rn(Wout[i]);
        }
    }
}

// ---------------- HMMA helpers ----------------
__device__ __forceinline__ void mma16816(float* c, const uint32_t* a, const uint32_t* b) {
    asm volatile(
        "mma.sync.aligned.m16n8k16.row.col.f32.f16.f16.f32 "
        "{%0,%1,%2,%3}, {%4,%5,%6,%7}, {%8,%9}, {%0,%1,%2,%3};\n"
        : "+f"(c[0]), "+f"(c[1]), "+f"(c[2]), "+f"(c[3])
        : "r"(a[0]), "r"(a[1]), "r"(a[2]), "r"(a[3]), "r"(b[0]), "r"(b[1]));
}

// ---------------- HMMA GEMM (fp32 out + bias): h = A[8192,K] @ Wt^T + b ----------------
__global__ __launch_bounds__(256) void gemm_hmma_f(
    const __half* __restrict__ A, const __half* __restrict__ Wt,
    const float* __restrict__ bias, float* __restrict__ C, int K)
{
    __shared__ __half As[128][40];
    __shared__ __half Bs[64][40];

    int cl = blockIdx.y;
    const __half* Ab = A + (size_t)cl * NP * K;
    float* Cb = C + (size_t)cl * NP * SCC;
    int row0 = blockIdx.x * 128;
    int tid = threadIdx.x, lane = tid & 31, warp = tid >> 5;
    int wm = warp >> 1, wn = warp & 1;
    int g = lane >> 2, tig = lane & 3;

    float acc[2][4][4];
#pragma unroll
    for (int am = 0; am < 2; am++)
#pragma unroll
        for (int an = 0; an < 4; an++)
#pragma unroll
            for (int d = 0; d < 4; d++) acc[am][an][d] = 0.f;

    for (int k0 = 0; k0 < K; k0 += 32) {
#pragma unroll
        for (int s = 0; s < 2; s++) {
            int ch = tid + s * 256;
            int r = ch >> 2, k8 = (ch & 3) * 8;
            *reinterpret_cast<uint4*>(&As[r][k8]) =
                *reinterpret_cast<const uint4*>(&Ab[(size_t)(row0 + r) * K + k0 + k8]);
        }
        {
            int n = tid >> 2, k8 = (tid & 3) * 8;
            *reinterpret_cast<uint4*>(&Bs[n][k8]) =
                *reinterpret_cast<const uint4*>(&Wt[(size_t)n * K + k0 + k8]);
        }
        __syncthreads();

#pragma unroll
        for (int ks = 0; ks < 32; ks += 16) {
            uint32_t a[2][4], b[4][2];
#pragma unroll
            for (int am = 0; am < 2; am++) {
                int r = wm * 32 + am * 16 + g;
                a[am][0] = *reinterpret_cast<const uint32_t*>(&As[r][ks + tig * 2]);
                a[am][1] = *reinterpret_cast<const uint32_t*>(&As[r + 8][ks + tig * 2]);
                a[am][2] = *reinterpret_cast<const uint32_t*>(&As[r][ks + tig * 2 + 8]);
                a[am][3] = *reinterpret_cast<const uint32_t*>(&As[r + 8][ks + tig * 2 + 8]);
            }
#pragma unroll
            for (int an = 0; an < 4; an++) {
                int n = wn * 32 + an * 8 + g;
                b[an][0] = *reinterpret_cast<const uint32_t*>(&Bs[n][ks + tig * 2]);
                b[an][1] = *reinterpret_cast<const uint32_t*>(&Bs[n][ks + tig * 2 + 8]);
            }
#pragma unroll
            for (int am = 0; am < 2; am++)
#pragma unroll
                for (int an = 0; an < 4; an++)
                    mma16816(acc[am][an], a[am], b[an]);
        }
        __syncthreads();
    }

#pragma unroll
    for (int am = 0; am < 2; am++)
#pragma unroll
        for (int an = 0; an < 4; an++) {
            int r = row0 + wm * 32 + am * 16 + g;
            int c = wn * 32 + an * 8 + tig * 2;
            float bv0 = bias[c], bv1 = bias[c + 1];
            float2 v0; v0.x = acc[am][an][0] + bv0; v0.y = acc[am][an][1] + bv1;
            float2 v1; v1.x = acc[am][an][2] + bv0; v1.y = acc[am][an][3] + bv1;
            *reinterpret_cast<float2*>(&Cb[(size_t)r * SCC + c]) = v0;
            *reinterpret_cast<float2*>(&Cb[(size_t)(r + 8) * SCC + c]) = v1;
        }
}

// ---------------- kNN: sorted order, 4 lanes per query (R11 version, measured) ----------------
__global__ __launch_bounds__(KNN_TPB) void knn_grid(
    const int* __restrict__ start, const float4* __restrict__ sorted,
    int* __restrict__ out_idx, int* __restrict__ out_cnt)
{
    extern __shared__ char smraw[];
    float* smd = (float*)smraw;                          // [128][33]
    int*   smi = (int*)(smraw + KNN_TPB * 33 * 4);       // [128][33]
    int*   s_keep = (int*)(smraw + KNN_TPB * 33 * 8);    // [128]

    int cl = blockIdx.y;
    int tid = threadIdx.x;
    int lq = tid & 3;
    int quad = tid >> 2;
    int s = blockIdx.x * KNN_QPB + quad;

    const int* st = start + cl * 513;
    const float4* srt = sorted + (size_t)cl * NP;

    float4 q4 = srt[s];
    float qx = q4.x, qy = q4.y, qz = q4.z;
    int orig = __float_as_int(q4.w);
    const float R2 = 0.0144f;

    int cx = (int)(qx * 8.0f); cx = cx < 0 ? 0 : (cx > 7 ? 7 : cx);
    int cy = (int)(qy * 8.0f); cy = cy < 0 ? 0 : (cy > 7 ? 7 : cy);
    int cz = (int)(qz * 8.0f); cz = cz < 0 ? 0 : (cz > 7 ? 7 : cz);
    int xlo = cx > 0 ? cx - 1 : 0, xhi = cx < 7 ? cx + 1 : 7;
    int ylo = cy > 0 ? cy - 1 : 0, yhi = cy < 7 ? cy + 1 : 7;
    int zlo = cz > 0 ? cz - 1 : 0, zhi = cz < 7 ? cz + 1 : 7;

    float* md = smd + tid * 33;
    int*   mi = smi + tid * 33;
    int keep = 0;
    float cm = 0.f; int ca = 0;

    for (int z = zlo; z <= zhi; z++)
        for (int y = ylo; y <= yhi; y++) {
            int rowcell = (z * 8 + y) * 8;
            int jb = st[rowcell + xlo];
            int je = st[rowcell + xhi + 1];
#pragma unroll 2
            for (int j = jb + lq; j < je; j += 4) {
                float4 pc = srt[j];
                float dx = __fsub_rn(qx, pc.x);
                float dy = __fsub_rn(qy, pc.y);
                float dz = __fsub_rn(qz, pc.z);
                float d2 = __fadd_rn(__fadd_rn(__fmul_rn(dx, dx), __fmul_rn(dy, dy)),
                                     __fmul_rn(dz, dz));
                if (d2 <= R2) {
                    if (keep < 32) {
                        md[keep] = d2; mi[keep] = __float_as_int(pc.w); keep++;
                        if (keep == 32) {
                            cm = md[0]; ca = 0;
#pragma unroll
                            for (int u = 1; u < 32; u++) { float v = md[u]; if (v > cm) { cm = v; ca = u; } }
                        }
                    } else if (d2 < cm) {
                        md[ca] = d2; mi[ca] = __float_as_int(pc.w);
                        cm = md[0]; ca = 0;
#pragma unroll
                        for (int u = 1; u < 32; u++) { float v = md[u]; if (v > cm) { cm = v; ca = u; } }
                    }
                }
            }
        }

    s_keep[tid] = keep;
    __syncwarp();

    if (lq == 0) {
        for (int l = 1; l < 4; l++) {
            const float* od = smd + (tid + l) * 33;
            const int*   oi2 = smi + (tid + l) * 33;
            int oc = s_keep[tid + l];
            for (int e = 0; e < oc; e++) {
                float d2 = od[e];
                int ix = oi2[e];
                if (keep < 32) {
                    md[keep] = d2; mi[keep] = ix; keep++;
                    if (keep == 32) {
                        cm = md[0]; ca = 0;
#pragma unroll
                        for (int u = 1; u < 32; u++) { float v = md[u]; if (v > cm) { cm = v; ca = u; } }
                    }
                } else if (d2 < cm) {
                    md[ca] = d2; mi[ca] = ix;
                    cm = md[0]; ca = 0;
#pragma unroll
                    for (int u = 1; u < 32; u++) { float v = md[u]; if (v > cm) { cm = v; ca = u; } }
                }
            }
        }
        int* oi = out_idx + ((size_t)cl * NP + orig) * 32;
        for (int u = 0; u < 32; u++) oi[u] = (u < keep) ? mi[u] : 0;
        out_cnt[cl * NP + orig] = keep;
    }
}

// ---------------- KPConv aggregate (R12 256-thread version, measured 39.3us) ----------------
__global__ __launch_bounds__(256) void agg_kernel(
    const float* __restrict__ c0, const float* __restrict__ c1,
    const int* __restrict__ idx, const int* __restrict__ cntArr,
    const float* __restrict__ h, const float* __restrict__ kpts,
    __half* __restrict__ agg)
{
    __shared__ __align__(16) float s_infl[AGG_PTS][32][16];   // padded, float4 loads
    __shared__ int   s_idx[AGG_PTS][32];
    __shared__ float s_rel[AGG_PTS][32][3];
    __shared__ float s_kp[KPN][3];
    __shared__ int   s_cnt[AGG_PTS];

    int cl = blockIdx.y;
    const float* coords = cl ? c1 : c0;
    int p0 = blockIdx.x * AGG_PTS;
    int tid = threadIdx.x;
    size_t qbase = (size_t)cl * NP + p0;

    if (tid < KPN * 3) s_kp[tid / 3][tid % 3] = kpts[tid];
    if (tid < AGG_PTS) s_cnt[tid] = cntArr[qbase + tid];
#pragma unroll
    for (int s = 0; s < 2; s++) {
        int i = tid + s * 256;
        int pt = i >> 5, k = i & 31;
        s_idx[pt][k] = idx[(qbase + pt) * 32 + k];
    }
    __syncthreads();

#pragma unroll
    for (int s = 0; s < 2; s++) {
        int i = tid + s * 256;
        int pt = i >> 5, k = i & 31;
        int j = s_idx[pt][k], n = p0 + pt;
        s_rel[pt][k][0] = __fsub_rn(coords[3 * j],     coords[3 * n]);
        s_rel[pt][k][1] = __fsub_rn(coords[3 * j + 1], coords[3 * n + 1]);
        s_rel[pt][k][2] = __fsub_rn(coords[3 * j + 2], coords[3 * n + 2]);
    }
    __syncthreads();

#pragma unroll
    for (int s = 0; s < 2; s++) {
        int i = tid + s * 256;
        int pt = i >> 5, k = i & 31;
        float rx = s_rel[pt][k][0], ry = s_rel[pt][k][1], rz = s_rel[pt][k][2];
        bool valid = k < s_cnt[pt];
#pragma unroll
        for (int p = 0; p < KPN; p++) {
            float dx = rx - s_kp[p][0];
            float dy = ry - s_kp[p][1];
            float dz = rz - s_kp[p][2];
            float dist = sqrtf(dx * dx + dy * dy + dz * dz);
            float w = fmaxf(1.0f - dist * (1.0f / 0.096f), 0.0f);
            s_infl[pt][k][p] = valid ? w : 0.0f;
        }
        s_infl[pt][k][15] = 0.0f;
    }
    __syncthreads();

    int pt = tid >> 4;
    int c4 = (tid & 15) << 2;
    const float* hcl = h + (size_t)cl * NP * SCC;

    float acc[KPN][4];
#pragma unroll
    for (int p = 0; p < KPN; p++)
#pragma unroll
        for (int d = 0; d < 4; d++) acc[p][d] = 0.f;

    float4 hv = *reinterpret_cast<const float4*>(&hcl[(size_t)s_idx[pt][0] * SCC + c4]);
#pragma unroll
    for (int k = 0; k < 32; k++) {
        float4 nxt;
        if (k < 31)
            nxt = *reinterpret_cast<const float4*>(&hcl[(size_t)s_idx[pt][k + 1] * SCC + c4]);
        const float4* wf = reinterpret_cast<const float4*>(&s_infl[pt][k][0]);
        float4 w0 = wf[0], w1 = wf[1], w2 = wf[2], w3 = wf[3];
        acc[0][0] += w0.x * hv.x; acc[0][1] += w0.x * hv.y; acc[0][2] += w0.x * hv.z; acc[0][3] += w0.x * hv.w;
        acc[1][0] += w0.y * hv.x; acc[1][1] += w0.y * hv.y; acc[1][2] += w0.y * hv.z; acc[1][3] += w0.y * hv.w;
        acc[2][0] += w0.z * hv.x; acc[2][1] += w0.z * hv.y; acc[2][2] += w0.z * hv.z; acc[2][3] += w0.z * hv.w;
        acc[3][0] += w0.w * hv.x; acc[3][1] += w0.w * hv.y; acc[3][2] += w0.w * hv.z; acc[3][3] += w0.w * hv.w;
        acc[4][0] += w1.x * hv.x; acc[4][1] += w1.x * hv.y; acc[4][2] += w1.x * hv.z; acc[4][3] += w1.x * hv.w;
        acc[5][0] += w1.y * hv.x; acc[5][1] += w1.y * hv.y; acc[5][2] += w1.y * hv.z; acc[5][3] += w1.y * hv.w;
        acc[6][0] += w1.z * hv.x; acc[6][1] += w1.z * hv.y; acc[6][2] += w1.z * hv.z; acc[6][3] += w1.z * hv.w;
        acc[7][0] += w1.w * hv.x; acc[7][1] += w1.w * hv.y; acc[7][2] += w1.w * hv.z; acc[7][3] += w1.w * hv.w;
        acc[8][0] += w2.x * hv.x; acc[8][1] += w2.x * hv.y; acc[8][2] += w2.x * hv.z; acc[8][3] += w2.x * hv.w;
        acc[9][0] += w2.y * hv.x; acc[9][1] += w2.y * hv.y; acc[9][2] += w2.y * hv.z; acc[9][3] += w2.y * hv.w;
        acc[10][0] += w2.z * hv.x; acc[10][1] += w2.z * hv.y; acc[10][2] += w2.z * hv.z; acc[10][3] += w2.z * hv.w;
        acc[11][0] += w2.w * hv.x; acc[11][1] += w2.w * hv.y; acc[11][2] += w2.w * hv.z; acc[11][3] += w2.w * hv.w;
        acc[12][0] += w3.x * hv.x; acc[12][1] += w3.x * hv.y; acc[12][2] += w3.x * hv.z; acc[12][3] += w3.x * hv.w;
        acc[13][0] += w3.y * hv.x; acc[13][1] += w3.y * hv.y; acc[13][2] += w3.y * hv.z; acc[13][3] += w3.y * hv.w;
        acc[14][0] += w3.z * hv.x; acc[14][1] += w3.z * hv.y; acc[14][2] += w3.z * hv.z; acc[14][3] += w3.z * hv.w;
        hv = nxt;
    }

    __half* o = agg + (qbase + pt) * KDIM + c4;
#pragma unroll
    for (int p = 0; p < KPN; p++) {
        __half2 h01 = __floats2half2_rn(acc[p][0], acc[p][1]);
        __half2 h23 = __floats2half2_rn(acc[p][2], acc[p][3]);
        uint2 pk;
        pk.x = *reinterpret_cast<unsigned int*>(&h01);
        pk.y = *reinterpret_cast<unsigned int*>(&h23);
        *reinterpret_cast<uint2*>(&o[p * SCC]) = pk;
    }
}

// ---------------- HMMA GEMM 1: h2(fp16) = agg[8192,960] @ Wkp[960,64] ----------------
__global__ __launch_bounds__(256) void gemm_hmma(
    const __half* __restrict__ A, const __half* __restrict__ Wt,
    __half* __restrict__ C)
{
    __shared__ __half As[128][40];
    __shared__ __half Bs[64][40];

    int cl = blockIdx.y;
    const __half* Ab = A + (size_t)cl * NP * KDIM;
    __half* Cb = C + (size_t)cl * NP * SCC;
    int row0 = blockIdx.x * 128;
    int tid = threadIdx.x, lane = tid & 31, warp = tid >> 5;
    int wm = warp >> 1, wn = warp & 1;
    int g = lane >> 2, tig = lane & 3;

    float acc[2][4][4];
#pragma unroll
    for (int am = 0; am < 2; am++)
#pragma unroll
        for (int an = 0; an < 4; an++)
#pragma unroll
            for (int d = 0; d < 4; d++) acc[am][an][d] = 0.f;

    for (int k0 = 0; k0 < KDIM; k0 += 32) {
#pragma unroll
        for (int s = 0; s < 2; s++) {
            int ch = tid + s * 256;
            int r = ch >> 2, k8 = (ch & 3) * 8;
            *reinterpret_cast<uint4*>(&As[r][k8]) =
                *reinterpret_cast<const uint4*>(&Ab[(size_t)(row0 + r) * KDIM + k0 + k8]);
        }
        {
            int n = tid >> 2, k8 = (tid & 3) * 8;
            *reinterpret_cast<uint4*>(&Bs[n][k8]) =
                *reinterpret_cast<const uint4*>(&Wt[(size_t)n * KDIM + k0 + k8]);
        }
        __syncthreads();

#pragma unroll
        for (int ks = 0; ks < 32; ks += 16) {
            uint32_t a[2][4], b[4][2];
#pragma unroll
            for (int am = 0; am < 2; am++) {
                int r = wm * 32 + am * 16 + g;
                a[am][0] = *reinterpret_cast<const uint32_t*>(&As[r][ks + tig * 2]);
                a[am][1] = *reinterpret_cast<const uint32_t*>(&As[r + 8][ks + tig * 2]);
                a[am][2] = *reinterpret_cast<const uint32_t*>(&As[r][ks + tig * 2 + 8]);
                a[am][3] = *reinterpret_cast<const uint32_t*>(&As[r + 8][ks + tig * 2 + 8]);
            }
#pragma unroll
            for (int an = 0; an < 4; an++) {
                int n = wn * 32 + an * 8 + g;
                b[an][0] = *reinterpret_cast<const uint32_t*>(&Bs[n][ks + tig * 2]);
                b[an][1] = *reinterpret_cast<const uint32_t*>(&Bs[n][ks + tig * 2 + 8]);
            }
#pragma unroll
            for (int am = 0; am < 2; am++)
#pragma unroll
                for (int an = 0; an < 4; an++)
                    mma16816(acc[am][an], a[am], b[an]);
        }
        __syncthreads();
    }

#pragma unroll
    for (int am = 0; am < 2; am++)
#pragma unroll
        for (int an = 0; an < 4; an++) {
            int r = row0 + wm * 32 + am * 16 + g;
            int c = wn * 32 + an * 8 + tig * 2;
            __half2 v0 = __floats2half2_rn(acc[am][an][0], acc[am][an][1]);
            __half2 v1 = __floats2half2_rn(acc[am][an][2], acc[am][an][3]);
            *reinterpret_cast<__half2*>(&Cb[(size_t)r * SCC + c]) = v0;
            *reinterpret_cast<__half2*>(&Cb[(size_t)(r + 8) * SCC + c]) = v1;
        }
}

// ---------------- HMMA GEMM 2: y = h2[8192,64] @ W_out[64,256] + b + BN partials ----------------
__global__ __launch_bounds__(256) void gemm_hmma2(
    const __half* __restrict__ A, const __half* __restrict__ Wt2,
    const float* __restrict__ bias, float* __restrict__ C,
    float* __restrict__ part)
{
    __shared__ __half As[128][72];
    __shared__ __half Bs[128][72];
    __shared__ float s_red[2][4][128];

    int cl = blockIdx.z;
    const __half* Ab = A + (size_t)cl * NP * SCC;
    float* Cb = C + (size_t)cl * NP * OUTC;
    int row0 = blockIdx.x * 128;
    int col0 = blockIdx.y * 128;
    int tid = threadIdx.x, lane = tid & 31, warp = tid >> 5;
    int wm = warp >> 1, wn = warp & 1;
    int g = lane >> 2, tig = lane & 3;

#pragma unroll
    for (int s = 0; s < 4; s++) {
        int ch = tid + s * 256;
        int r = ch >> 3, k8 = (ch & 7) * 8;
        *reinterpret_cast<uint4*>(&As[r][k8]) =
            *reinterpret_cast<const uint4*>(&Ab[(size_t)(row0 + r) * SCC + k8]);
        *reinterpret_cast<uint4*>(&Bs[r][k8]) =
            *reinterpret_cast<const uint4*>(&Wt2[(size_t)(col0 + r) * SCC + k8]);
    }
    __syncthreads();

    float acc[2][8][4];
#pragma unroll
    for (int am = 0; am < 2; am++)
#pragma unroll
        for (int an = 0; an < 8; an++)
#pragma unroll
            for (int d = 0; d < 4; d++) acc[am][an][d] = 0.f;

#pragma unroll
    for (int ks = 0; ks < 64; ks += 16) {
        uint32_t a[2][4], b[8][2];
#pragma unroll
        for (int am = 0; am < 2; am++) {
            int r = wm * 32 + am * 16 + g;
            a[am][0] = *reinterpret_cast<const uint32_t*>(&As[r][ks + tig * 2]);
            a[am][1] = *reinterpret_cast<const uint32_t*>(&As[r + 8][ks + tig * 2]);
            a[am][2] = *reinterpret_cast<const uint32_t*>(&As[r][ks + tig * 2 + 8]);
            a[am][3] = *reinterpret_cast<const uint32_t*>(&As[r + 8][ks + tig * 2 + 8]);
        }
#pragma unroll
        for (int an = 0; an < 8; an++) {
            int n = wn * 64 + an * 8 + g;
            b[an][0] = *reinterpret_cast<const uint32_t*>(&Bs[n][ks + tig * 2]);
            b[an][1] = *reinterpret_cast<const uint32_t*>(&Bs[n][ks + tig * 2 + 8]);
        }
#pragma unroll
        for (int am = 0; am < 2; am++)
#pragma unroll
            for (int an = 0; an < 8; an++)
                mma16816(acc[am][an], a[am], b[an]);
    }

#pragma unroll
    for (int an = 0; an < 8; an++) {
        int c = wn * 64 + an * 8 + tig * 2;
        float bv0 = bias[col0 + c], bv1 = bias[col0 + c + 1];
        float s0 = 0.f, s1 = 0.f, q0 = 0.f, q1 = 0.f;
#pragma unroll
        for (int am = 0; am < 2; am++) {
            int r = row0 + wm * 32 + am * 16 + g;
            float v0 = acc[am][an][0] + bv0, v1 = acc[am][an][1] + bv1;
            float v2 = acc[am][an][2] + bv0, v3 = acc[am][an][3] + bv1;
            float2 w0; w0.x = v0; w0.y = v1;
            float2 w1; w1.x = v2; w1.y = v3;
            *reinterpret_cast<float2*>(&Cb[(size_t)r * OUTC + col0 + c]) = w0;
            *reinterpret_cast<float2*>(&Cb[(size_t)(r + 8) * OUTC + col0 + c]) = w1;
            s0 += v0 + v2; s1 += v1 + v3;
            q0 += v0 * v0 + v2 * v2; q1 += v1 * v1 + v3 * v3;
        }
#pragma unroll
        for (int m = 4; m <= 16; m <<= 1) {
            s0 += __shfl_xor_sync(0xffffffffu, s0, m);
            s1 += __shfl_xor_sync(0xffffffffu, s1, m);
            q0 += __shfl_xor_sync(0xffffffffu, q0, m);
            q1 += __shfl_xor_sync(0xffffffffu, q1, m);
        }
        if (g == 0) {
            s_red[0][wm][c] = s0; s_red[0][wm][c + 1] = s1;
            s_red[1][wm][c] = q0; s_red[1][wm][c + 1] = q1;
        }
    }
    __syncthreads();
    {
        int c = tid & 127, s = tid >> 7;
        float v = s_red[s][0][c] + s_red[s][1][c] + s_red[s][2][c] + s_red[s][3][c];
        part[((size_t)(cl * 2 + s) * 64 + blockIdx.x) * OUTC + col0 + c] = v;
    }
}

// ---------------- batch norm finalize + apply ----------------
__global__ __launch_bounds__(256) void bn_final(const float* __restrict__ part,
                                                float* __restrict__ mu,
                                                float* __restrict__ rstd)
{
    int cl = blockIdx.x, ch = threadIdx.x;
    float s = 0.f, s2 = 0.f;
    for (int r = 0; r < 64; r++) {
        s  += part[((size_t)(cl * 2 + 0) * 64 + r) * OUTC + ch];
        s2 += part[((size_t)(cl * 2 + 1) * 64 + r) * OUTC + ch];
    }
    float m = s * (1.0f / 8192.0f);
    float v = s2 * (1.0f / 8192.0f) - m * m;
    v = v < 0.f ? 0.f : v;
    mu[cl * OUTC + ch]   = m;
    rstd[cl * OUTC + ch] = rsqrtf(v + 1e-5f);
}

__global__ __launch_bounds__(256) void bn_apply(float* __restrict__ y,
                                                const float* __restrict__ mu,
                                                const float* __restrict__ rstd,
                                                const float* __restrict__ gamma,
                                                const float* __restrict__ beta)
{
    size_t i4 = (size_t)blockIdx.x * blockDim.x + threadIdx.x;
    size_t base = i4 * 4;
    int ch = (int)(base & (OUTC - 1));
    int cl = (int)(base >> 21);
    float4 v = *reinterpret_cast<float4*>(&y[base]);
    const float* muc = mu + cl * OUTC + ch;
    const float* rsc = rstd + cl * OUTC + ch;
    const float* gc = gamma + ch;
    const float* bc = beta + ch;
    float t0 = gc[0] * (v.x - muc[0]) * rsc[0] + bc[0];
    float t1 = gc[1] * (v.y - muc[1]) * rsc[1] + bc[1];
    float t2 = gc[2] * (v.z - muc[2]) * rsc[2] + bc[2];
    float t3 = gc[3] * (v.w - muc[3]) * rsc[3] + bc[3];
    v.x = t0 > 0.f ? t0 : 0.1f * t0;
    v.y = t1 > 0.f ? t1 : 0.1f * t1;
    v.z = t2 > 0.f ? t2 : 0.1f * t2;
    v.w = t3 > 0.f ? t3 : 0.1f * t3;
    *reinterpret_cast<float4*>(&y[base]) = v;
}

// ---------------- launch ----------------
extern "C" void kernel_launch(void* const* d_in, const int* in_sizes, int n_in,
                              void* d_out, int out_size)
{
    const float* src    = (const float*)d_in[0];
    const float* tgt    = (const float*)d_in[1];
    const float* src_c  = (const float*)d_in[2];
    const float* tgt_c  = (const float*)d_in[3];
    const float* W_in   = (const float*)d_in[4];
    const float* b_in   = (const float*)d_in[5];
    const float* kpts   = (const float*)d_in[6];
    const float* W_kp   = (const float*)d_in[7];
    const float* W_out  = (const float*)d_in[8];
    const float* b_out  = (const float*)d_in[9];
    const float* gamma  = (const float*)d_in[10];
    const float* beta   = (const float*)d_in[11];
    float* out = (float*)d_out;

    void* p;
    cudaGetSymbolAddress(&p, g_xh);       __half* xhP   = (__half*)p;
    cudaGetSymbolAddress(&p, g_h);        float*  hP    = (float*)p;
    cudaGetSymbolAddress(&p, g_idx);      int*    idxP  = (int*)p;
    cudaGetSymbolAddress(&p, g_cnt);      int*    cntP  = (int*)p;
    cudaGetSymbolAddress(&p, g_agg);      __half* aggP  = (__half*)p;
    cudaGetSymbolAddress(&p, g_wt1);      __half* wt1P  = (__half*)p;
    cudaGetSymbolAddress(&p, g_wt);       __half* wtP   = (__half*)p;
    cudaGetSymbolAddress(&p, g_wt2);      __half* wt2P  = (__half*)p;
    cudaGetSymbolAddress(&p, g_h2);       __half* h2P   = (__half*)p;
    cudaGetSymbolAddress(&p, g_part);     float*  partP = (float*)p;
    cudaGetSymbolAddress(&p, g_mu);       float*  muP   = (float*)p;
    cudaGetSymbolAddress(&p, g_rstd);     float*  rstdP = (float*)p;
    cudaGetSymbolAddress(&p, g_cellstart);int*    cstP  = (int*)p;
    cudaGetSymbolAddress(&p, g_sorted);   float4* srtP  = (float4*)p;

    const int KNN_SMEM = KNN_TPB * 33 * 8 + KNN_TPB * 4;   // 34304 B
    cudaFuncSetAttribute(knn_grid, cudaFuncAttributeMaxDynamicSharedMemorySize, KNN_SMEM);

    // 0) grid build + all fp16 conversions (single launch)
    grid_build<<<BUILD_BLOCKS, 512>>>(src_c, tgt_c, src, tgt, W_in, W_kp, W_out,
                                      xhP, wt1P, wtP, wt2P, cstP, srtP);

    // 1) h = x @ W_in + b_in  (HMMA, fp32 out)
    gemm_hmma_f<<<dim3(NP / 128, 2), 256>>>(xhP, wt1P, b_in, hP, INC);

    // 2) grid kNN: sorted order, 4 lanes per query
    knn_grid<<<dim3(NP / KNN_QPB, 2), KNN_TPB, KNN_SMEM>>>(cstP, srtP, idxP, cntP);

    // 3) KPConv influence-weighted aggregation -> agg [N, 960] (fp16)
    agg_kernel<<<dim3(NP / AGG_PTS, 2), 256>>>(src_c, tgt_c, idxP, cntP, hP, kpts, aggP);

    // 4) h2(fp16) = agg @ W_kp  (HMMA)
    gemm_hmma<<<dim3(NP / 128, 2), 256>>>(aggP, wtP, h2P);

    // 5) y = h2 @ W_out + b_out -> d_out (HMMA) with fused BN partials
    gemm_hmma2<<<dim3(NP / 128, 2, 2), 256>>>(h2P, wt2P, b_out, out, partP);

    // 6) batch norm finalize + apply (in place on d_out)
    bn_final<<<2, 256>>>(partP, muP, rstdP);
    bn_apply<<<(2 * NP * OUTC / 4) / 256, 256>>>(out, muP, rstdP, gamma, beta);

    // 7) coords pass-through
    cudaMemcpyAsync(out + (size_t)2 * NP * OUTC, src_c, NP * 3 * sizeof(float),
                    cudaMemcpyDeviceToDevice);
    cudaMemcpyAsync(out + (size_t)2 * NP * OUTC + NP * 3, tgt_c, NP * 3 * sizeof(float),
                    cudaMemcpyDeviceToDevice);
}

// round 15
// speedup vs baseline: 1.1795x; 1.0793x over previous
#include <cuda_runtime.h>
#include <cuda_fp16.h>
#include <stdint.h>
#include <math.h>

#define NP    8192
#define INC   256
#define SCC   64
#define OUTC  256
#define KPN   15
#define KDIM  (KPN * SCC)     // 960
#define KNN_TPB 128           // 32 queries/block x 4 lanes/query
#define KNN_QPB 32

// ---------------- scratch (__device__ globals, no allocations) ----------------
__device__ __align__(256) __half g_xh  [2 * NP * INC];                 // 8 MB fp16 inputs
__device__ __align__(256) __half g_h   [2 * NP * SCC];                 // 2 MB fp16
__device__ __align__(256) int    g_idx [2 * NP * 32];                  // 2 MB
__device__ __align__(256) int    g_cnt [2 * NP];
__device__ __align__(256) __half g_agg [(size_t)2 * NP * KDIM];        // 30 MB (fp16)
__device__ __align__(256) __half g_wt1 [SCC * INC];                    // W_in^T fp16 [64][256]
__device__ __align__(256) __half g_wt  [SCC * KDIM];                   // W_kp^T fp16 [64][960]
__device__ __align__(256) __half g_wt2 [OUTC * SCC];                   // W_out^T fp16 [256][64]
__device__ __align__(256) __half g_h2  [2 * NP * SCC];                 // 2 MB fp16
__device__ __align__(256) float  g_part[2 * 2 * 64 * OUTC];
__device__ __align__(256) float  g_mu  [2 * OUTC];
__device__ __align__(256) float  g_rstd[2 * OUTC];
__device__ __align__(256) int    g_cellstart[2 * 513];
__device__ __align__(256) float4 g_sorted   [2 * NP];   // xyz + original index (bits)

// ---------------- combined grid build + fp16 conversions (one launch) ----------------
__device__ __forceinline__ int cell_of(float x, float y, float z) {
    int cx = (int)(x * 8.0f); cx = cx < 0 ? 0 : (cx > 7 ? 7 : cx);
    int cy = (int)(y * 8.0f); cy = cy < 0 ? 0 : (cy > 7 ? 7 : cy);
    int cz = (int)(z * 8.0f); cz = cz < 0 ? 0 : (cz > 7 ? 7 : cz);
    return (cz * 8 + cy) * 8 + cx;
}

#define BUILD_BLOCKS 66

__global__ __launch_bounds__(512) void grid_build(
    const float* __restrict__ c0, const float* __restrict__ c1,
    const float* __restrict__ src, const float* __restrict__ tgt,
    const float* __restrict__ Win, const float* __restrict__ Wkp,
    const float* __restrict__ Wout,
    __half* __restrict__ xh, __half* __restrict__ wt1,
    __half* __restrict__ wt, __half* __restrict__ wt2,
    int* __restrict__ start, float4* __restrict__ sorted)
{
    int b = blockIdx.x;
    int t = threadIdx.x;
    if (b < 2) {
        __shared__ short s_cell[NP];    // 16 KB
        __shared__ int s_cnt[512], s_sc[512], s_fill[512];
        const float* c = b ? c1 : c0;
        s_cnt[t] = 0; s_fill[t] = 0;
        __syncthreads();
#pragma unroll
        for (int i = 0; i < 16; i++) {
            int p = t + i * 512;
            int cell = cell_of(c[3 * p], c[3 * p + 1], c[3 * p + 2]);
            s_cell[p] = (short)cell;
            atomicAdd(&s_cnt[cell], 1);
        }
        __syncthreads();
        s_sc[t] = s_cnt[t];
        __syncthreads();
#pragma unroll
        for (int off = 1; off < 512; off <<= 1) {
            int v = (t >= off) ? s_sc[t - off] : 0;
            __syncthreads();
            s_sc[t] += v;
            __syncthreads();
        }
        start[b * 513 + t + 1] = s_sc[t];
        if (t == 0) start[b * 513] = 0;
        __syncthreads();
#pragma unroll
        for (int i = 0; i < 16; i++) {
            int p = t + i * 512;
            int cell = s_cell[p];
            int pos = s_sc[cell] - s_cnt[cell] + atomicAdd(&s_fill[cell], 1);
            sorted[b * NP + pos] = make_float4(c[3 * p], c[3 * p + 1], c[3 * p + 2],
                                               __int_as_float(p));
        }
    } else {
        int gt = (b - 2) * 512 + t;
        int stride = (BUILD_BLOCKS - 2) * 512;
        for (int i4 = gt; i4 < (2 * NP * INC) / 4; i4 += stride) {
            size_t base = (size_t)i4 * 4;
            int cl = (int)(base >> 21);
            size_t off = base & ((size_t)NP * INC - 1);
            float4 v = *reinterpret_cast<const float4*>(&(cl ? tgt : src)[off]);
            __half2 h01 = __floats2half2_rn(v.x, v.y);
            __half2 h23 = __floats2half2_rn(v.z, v.w);
            uint2 pk;
            pk.x = *reinterpret_cast<unsigned int*>(&h01);
            pk.y = *reinterpret_cast<unsigned int*>(&h23);
            *reinterpret_cast<uint2*>(&xh[base]) = pk;
        }
        for (int i = gt; i < INC * SCC; i += stride) {
            int k = i >> 6, n = i & 63;
            wt1[n * INC + k] = __float2half_rn(Win[i]);
        }
        for (int i = gt; i < KDIM * SCC; i += stride) {
            int k = i >> 6, n = i & 63;
            wt[n * KDIM + k] = __float2half_rn(Wkp[i]);
        }
        for (int i = gt; i < SCC * OUTC; i += stride) {
            int k = i >> 8, n = i & 255;
            wt2[n * SCC + k] = __float2half_rn(Wout[i]);
        }
    }
}

// ---------------- HMMA helpers ----------------
__device__ __forceinline__ void mma16816(float* c, const uint32_t* a, const uint32_t* b) {
    asm volatile(
        "mma.sync.aligned.m16n8k16.row.col.f32.f16.f16.f32 "
        "{%0,%1,%2,%3}, {%4,%5,%6,%7}, {%8,%9}, {%0,%1,%2,%3};\n"
        : "+f"(c[0]), "+f"(c[1]), "+f"(c[2]), "+f"(c[3])
        : "r"(a[0]), "r"(a[1]), "r"(a[2]), "r"(a[3]), "r"(b[0]), "r"(b[1]));
}

// ---------------- HMMA GEMM (fp16 out + bias): h = A[8192,K] @ Wt^T + b ----------------
__global__ __launch_bounds__(256) void gemm_hmma_fh(
    const __half* __restrict__ A, const __half* __restrict__ Wt,
    const float* __restrict__ bias, __half* __restrict__ C, int K)
{
    __shared__ __half As[128][40];
    __shared__ __half Bs[64][40];

    int cl = blockIdx.y;
    const __half* Ab = A + (size_t)cl * NP * K;
    __half* Cb = C + (size_t)cl * NP * SCC;
    int row0 = blockIdx.x * 128;
    int tid = threadIdx.x, lane = tid & 31, warp = tid >> 5;
    int wm = warp >> 1, wn = warp & 1;
    int g = lane >> 2, tig = lane & 3;

    float acc[2][4][4];
#pragma unroll
    for (int am = 0; am < 2; am++)
#pragma unroll
        for (int an = 0; an < 4; an++)
#pragma unroll
            for (int d = 0; d < 4; d++) acc[am][an][d] = 0.f;

    for (int k0 = 0; k0 < K; k0 += 32) {
#pragma unroll
        for (int s = 0; s < 2; s++) {
            int ch = tid + s * 256;
            int r = ch >> 2, k8 = (ch & 3) * 8;
            *reinterpret_cast<uint4*>(&As[r][k8]) =
                *reinterpret_cast<const uint4*>(&Ab[(size_t)(row0 + r) * K + k0 + k8]);
        }
        {
            int n = tid >> 2, k8 = (tid & 3) * 8;
            *reinterpret_cast<uint4*>(&Bs[n][k8]) =
                *reinterpret_cast<const uint4*>(&Wt[(size_t)n * K + k0 + k8]);
        }
        __syncthreads();

#pragma unroll
        for (int ks = 0; ks < 32; ks += 16) {
            uint32_t a[2][4], b[4][2];
#pragma unroll
            for (int am = 0; am < 2; am++) {
                int r = wm * 32 + am * 16 + g;
                a[am][0] = *reinterpret_cast<const uint32_t*>(&As[r][ks + tig * 2]);
                a[am][1] = *reinterpret_cast<const uint32_t*>(&As[r + 8][ks + tig * 2]);
                a[am][2] = *reinterpret_cast<const uint32_t*>(&As[r][ks + tig * 2 + 8]);
                a[am][3] = *reinterpret_cast<const uint32_t*>(&As[r + 8][ks + tig * 2 + 8]);
            }
#pragma unroll
            for (int an = 0; an < 4; an++) {
                int n = wn * 32 + an * 8 + g;
                b[an][0] = *reinterpret_cast<const uint32_t*>(&Bs[n][ks + tig * 2]);
                b[an][1] = *reinterpret_cast<const uint32_t*>(&Bs[n][ks + tig * 2 + 8]);
            }
#pragma unroll
            for (int am = 0; am < 2; am++)
#pragma unroll
                for (int an = 0; an < 4; an++)
                    mma16816(acc[am][an], a[am], b[an]);
        }
        __syncthreads();
    }

#pragma unroll
    for (int am = 0; am < 2; am++)
#pragma unroll
        for (int an = 0; an < 4; an++) {
            int r = row0 + wm * 32 + am * 16 + g;
            int c = wn * 32 + an * 8 + tig * 2;
            float bv0 = bias[c], bv1 = bias[c + 1];
            __half2 v0 = __floats2half2_rn(acc[am][an][0] + bv0, acc[am][an][1] + bv1);
            __half2 v1 = __floats2half2_rn(acc[am][an][2] + bv0, acc[am][an][3] + bv1);
            *reinterpret_cast<__half2*>(&Cb[(size_t)r * SCC + c]) = v0;
            *reinterpret_cast<__half2*>(&Cb[(size_t)(r + 8) * SCC + c]) = v1;
        }
}

// ---------------- kNN: sorted order, 4 lanes per query (measured) ----------------
__global__ __launch_bounds__(KNN_TPB) void knn_grid(
    const int* __restrict__ start, const float4* __restrict__ sorted,
    int* __restrict__ out_idx, int* __restrict__ out_cnt)
{
    extern __shared__ char smraw[];
    float* smd = (float*)smraw;                          // [128][33]
    int*   smi = (int*)(smraw + KNN_TPB * 33 * 4);       // [128][33]
    int*   s_keep = (int*)(smraw + KNN_TPB * 33 * 8);    // [128]

    int cl = blockIdx.y;
    int tid = threadIdx.x;
    int lq = tid & 3;
    int quad = tid >> 2;
    int s = blockIdx.x * KNN_QPB + quad;

    const int* st = start + cl * 513;
    const float4* srt = sorted + (size_t)cl * NP;

    float4 q4 = srt[s];
    float qx = q4.x, qy = q4.y, qz = q4.z;
    int orig = __float_as_int(q4.w);
    const float R2 = 0.0144f;

    int cx = (int)(qx * 8.0f); cx = cx < 0 ? 0 : (cx > 7 ? 7 : cx);
    int cy = (int)(qy * 8.0f); cy = cy < 0 ? 0 : (cy > 7 ? 7 : cy);
    int cz = (int)(qz * 8.0f); cz = cz < 0 ? 0 : (cz > 7 ? 7 : cz);
    int xlo = cx > 0 ? cx - 1 : 0, xhi = cx < 7 ? cx + 1 : 7;
    int ylo = cy > 0 ? cy - 1 : 0, yhi = cy < 7 ? cy + 1 : 7;
    int zlo = cz > 0 ? cz - 1 : 0, zhi = cz < 7 ? cz + 1 : 7;

    float* md = smd + tid * 33;
    int*   mi = smi + tid * 33;
    int keep = 0;
    float cm = 0.f; int ca = 0;

    for (int z = zlo; z <= zhi; z++)
        for (int y = ylo; y <= yhi; y++) {
            int rowcell = (z * 8 + y) * 8;
            int jb = st[rowcell + xlo];
            int je = st[rowcell + xhi + 1];
#pragma unroll 2
            for (int j = jb + lq; j < je; j += 4) {
                float4 pc = srt[j];
                float dx = __fsub_rn(qx, pc.x);
                float dy = __fsub_rn(qy, pc.y);
                float dz = __fsub_rn(qz, pc.z);
                float d2 = __fadd_rn(__fadd_rn(__fmul_rn(dx, dx), __fmul_rn(dy, dy)),
                                     __fmul_rn(dz, dz));
                if (d2 <= R2) {
                    if (keep < 32) {
                        md[keep] = d2; mi[keep] = __float_as_int(pc.w); keep++;
                        if (keep == 32) {
                            cm = md[0]; ca = 0;
#pragma unroll
                            for (int u = 1; u < 32; u++) { float v = md[u]; if (v > cm) { cm = v; ca = u; } }
                        }
                    } else if (d2 < cm) {
                        md[ca] = d2; mi[ca] = __float_as_int(pc.w);
                        cm = md[0]; ca = 0;
#pragma unroll
                        for (int u = 1; u < 32; u++) { float v = md[u]; if (v > cm) { cm = v; ca = u; } }
                    }
                }
            }
        }

    s_keep[tid] = keep;
    __syncwarp();

    if (lq == 0) {
        for (int l = 1; l < 4; l++) {
            const float* od = smd + (tid + l) * 33;
            const int*   oi2 = smi + (tid + l) * 33;
            int oc = s_keep[tid + l];
            for (int e = 0; e < oc; e++) {
                float d2 = od[e];
                int ix = oi2[e];
                if (keep < 32) {
                    md[keep] = d2; mi[keep] = ix; keep++;
                    if (keep == 32) {
                        cm = md[0]; ca = 0;
#pragma unroll
                        for (int u = 1; u < 32; u++) { float v = md[u]; if (v > cm) { cm = v; ca = u; } }
                    }
                } else if (d2 < cm) {
                    md[ca] = d2; mi[ca] = ix;
                    cm = md[0]; ca = 0;
#pragma unroll
                    for (int u = 1; u < 32; u++) { float v = md[u]; if (v > cm) { cm = v; ca = u; } }
                }
            }
        }
        int* oi = out_idx + ((size_t)cl * NP + orig) * 32;
        for (int u = 0; u < 32; u++) oi[u] = (u < keep) ? mi[u] : 0;
        out_cnt[cl * NP + orig] = keep;
    }
}

// ---------------- KPConv aggregate on TENSOR CORES: warp per point ----------------
// Per point: D[16(kp,pad)][64(ch)] = infl[16][32(nb)] @ nb_feats[32][64].
// Warp-local: lane k computes neighbor k's influences (fp16 -> smem A-tile),
// warp gathers 32 fp16 h-rows into smem B-tile, 16x m16n8k16 fp32-acc MMAs.
__global__ __launch_bounds__(256) void agg_mma(
    const float* __restrict__ c0, const float* __restrict__ c1,
    const int* __restrict__ idx, const int* __restrict__ cntArr,
    const __half* __restrict__ h, const float* __restrict__ kpts,
    __half* __restrict__ agg)
{
    __shared__ __half s_nb[8][32][72];     // 36864 B  (B tile, padded rows)
    __shared__ __half s_infl[8][16][40];   // 10240 B  (A tile, padded rows)
    __shared__ float s_kp[45];

    int tid = threadIdx.x, lane = tid & 31, w = tid >> 5;
    int cl = blockIdx.y;
    int pt = blockIdx.x * 8 + w;
    size_t q = (size_t)cl * NP + pt;
    const float* coords = cl ? c1 : c0;

    if (tid < 45) s_kp[tid] = kpts[tid];
    __syncthreads();

    // lane k owns neighbor k: rel + influences
    int j = idx[q * 32 + lane];
    int cnt = cntArr[q];
    float rx = __fsub_rn(coords[3 * j],     coords[3 * pt]);
    float ry = __fsub_rn(coords[3 * j + 1], coords[3 * pt + 1]);
    float rz = __fsub_rn(coords[3 * j + 2], coords[3 * pt + 2]);
    bool valid = lane < cnt;
#pragma unroll
    for (int p = 0; p < KPN; p++) {
        float dx = rx - s_kp[p * 3 + 0];
        float dy = ry - s_kp[p * 3 + 1];
        float dz = rz - s_kp[p * 3 + 2];
        float dist = sqrtf(dx * dx + dy * dy + dz * dz);
        float wgt = fmaxf(1.0f - dist * (1.0f / 0.096f), 0.0f);
        s_infl[w][p][lane] = __float2half_rn(valid ? wgt : 0.0f);
    }
    s_infl[w][15][lane] = __float2half_rn(0.0f);

    // gather 32 neighbor feature rows (64 halves each)
    const __half* hcl = h + (size_t)cl * NP * SCC;
    int r4 = lane >> 3, c8 = lane & 7;
#pragma unroll
    for (int i = 0; i < 8; i++) {
        int r = i * 4 + r4;
        int jr = __shfl_sync(0xffffffffu, j, r);
        uint4 v = *reinterpret_cast<const uint4*>(&hcl[(size_t)jr * SCC + c8 * 8]);
        *reinterpret_cast<uint4*>(&s_nb[w][r][c8 * 8]) = v;
    }
    __syncwarp();

    int g = lane >> 2, tig = lane & 3;
    float acc[8][4];
#pragma unroll
    for (int an = 0; an < 8; an++)
#pragma unroll
        for (int d = 0; d < 4; d++) acc[an][d] = 0.f;

#pragma unroll
    for (int ks = 0; ks < 32; ks += 16) {
        uint32_t a[4];
        a[0] = *reinterpret_cast<const uint32_t*>(&s_infl[w][g][ks + tig * 2]);
        a[1] = *reinterpret_cast<const uint32_t*>(&s_infl[w][g + 8][ks + tig * 2]);
        a[2] = *reinterpret_cast<const uint32_t*>(&s_infl[w][g][ks + tig * 2 + 8]);
        a[3] = *reinterpret_cast<const uint32_t*>(&s_infl[w][g + 8][ks + tig * 2 + 8]);
#pragma unroll
        for (int an = 0; an < 8; an++) {
            int n = an * 8 + g;
            uint32_t lo0 = *reinterpret_cast<const unsigned short*>(&s_nb[w][ks + tig * 2][n]);
            uint32_t hi0 = *reinterpret_cast<const unsigned short*>(&s_nb[w][ks + tig * 2 + 1][n]);
            uint32_t lo1 = *reinterpret_cast<const unsigned short*>(&s_nb[w][ks + tig * 2 + 8][n]);
            uint32_t hi1 = *reinterpret_cast<const unsigned short*>(&s_nb[w][ks + tig * 2 + 9][n]);
            uint32_t b[2];
            b[0] = lo0 | (hi0 << 16);
            b[1] = lo1 | (hi1 << 16);
            mma16816(acc[an], a, b);
        }
    }

    // epilogue: D rows g (p=g) and g+8 (p=g+8, skip p=15 pad)
    __half* o = agg + q * KDIM;
#pragma unroll
    for (int an = 0; an < 8; an++) {
        int c = an * 8 + tig * 2;
        __half2 v0 = __floats2half2_rn(acc[an][0], acc[an][1]);
        *reinterpret_cast<__half2*>(&o[g * SCC + c]) = v0;
        if (g < 7) {
            __half2 v1 = __floats2half2_rn(acc[an][2], acc[an][3]);
            *reinterpret_cast<__half2*>(&o[(g + 8) * SCC + c]) = v1;
        }
    }
}

// ---------------- HMMA GEMM 1: h2(fp16) = agg[8192,960] @ Wkp[960,64] ----------------
__global__ __launch_bounds__(256) void gemm_hmma(
    const __half* __restrict__ A, const __half* __restrict__ Wt,
    __half* __restrict__ C)
{
    __shared__ __half As[128][40];
    __shared__ __half Bs[64][40];

    int cl = blockIdx.y;
    const __half* Ab = A + (size_t)cl * NP * KDIM;
    __half* Cb = C + (size_t)cl * NP * SCC;
    int row0 = blockIdx.x * 128;
    int tid = threadIdx.x, lane = tid & 31, warp = tid >> 5;
    int wm = warp >> 1, wn = warp & 1;
    int g = lane >> 2, tig = lane & 3;

    float acc[2][4][4];
#pragma unroll
    for (int am = 0; am < 2; am++)
#pragma unroll
        for (int an = 0; an < 4; an++)
#pragma unroll
            for (int d = 0; d < 4; d++) acc[am][an][d] = 0.f;

    for (int k0 = 0; k0 < KDIM; k0 += 32) {
#pragma unroll
        for (int s = 0; s < 2; s++) {
            int ch = tid + s * 256;
            int r = ch >> 2, k8 = (ch & 3) * 8;
            *reinterpret_cast<uint4*>(&As[r][k8]) =
                *reinterpret_cast<const uint4*>(&Ab[(size_t)(row0 + r) * KDIM + k0 + k8]);
        }
        {
            int n = tid >> 2, k8 = (tid & 3) * 8;
            *reinterpret_cast<uint4*>(&Bs[n][k8]) =
                *reinterpret_cast<const uint4*>(&Wt[(size_t)n * KDIM + k0 + k8]);
        }
        __syncthreads();

#pragma unroll
        for (int ks = 0; ks < 32; ks += 16) {
            uint32_t a[2][4], b[4][2];
#pragma unroll
            for (int am = 0; am < 2; am++) {
                int r = wm * 32 + am * 16 + g;
                a[am][0] = *reinterpret_cast<const uint32_t*>(&As[r][ks + tig * 2]);
                a[am][1] = *reinterpret_cast<const uint32_t*>(&As[r + 8][ks + tig * 2]);
                a[am][2] = *reinterpret_cast<const uint32_t*>(&As[r][ks + tig * 2 + 8]);
                a[am][3] = *reinterpret_cast<const uint32_t*>(&As[r + 8][ks + tig * 2 + 8]);
            }
#pragma unroll
            for (int an = 0; an < 4; an++) {
                int n = wn * 32 + an * 8 + g;
                b[an][0] = *reinterpret_cast<const uint32_t*>(&Bs[n][ks + tig * 2]);
                b[an][1] = *reinterpret_cast<const uint32_t*>(&Bs[n][ks + tig * 2 + 8]);
            }
#pragma unroll
            for (int am = 0; am < 2; am++)
#pragma unroll
                for (int an = 0; an < 4; an++)
                    mma16816(acc[am][an], a[am], b[an]);
        }
        __syncthreads();
    }

#pragma unroll
    for (int am = 0; am < 2; am++)
#pragma unroll
        for (int an = 0; an < 4; an++) {
            int r = row0 + wm * 32 + am * 16 + g;
            int c = wn * 32 + an * 8 + tig * 2;
            __half2 v0 = __floats2half2_rn(acc[am][an][0], acc[am][an][1]);
            __half2 v1 = __floats2half2_rn(acc[am][an][2], acc[am][an][3]);
            *reinterpret_cast<__half2*>(&Cb[(size_t)r * SCC + c]) = v0;
            *reinterpret_cast<__half2*>(&Cb[(size_t)(r + 8) * SCC + c]) = v1;
        }
}

// ---------------- HMMA GEMM 2: y = h2[8192,64] @ W_out[64,256] + b + BN partials ----------------
__global__ __launch_bounds__(256) void gemm_hmma2(
    const __half* __restrict__ A, const __half* __restrict__ Wt2,
    const float* __restrict__ bias, float* __restrict__ C,
    float* __restrict__ part)
{
    __shared__ __half As[128][72];
    __shared__ __half Bs[128][72];
    __shared__ float s_red[2][4][128];

    int cl = blockIdx.z;
    const __half* Ab = A + (size_t)cl * NP * SCC;
    float* Cb = C + (size_t)cl * NP * OUTC;
    int row0 = blockIdx.x * 128;
    int col0 = blockIdx.y * 128;
    int tid = threadIdx.x, lane = tid & 31, warp = tid >> 5;
    int wm = warp >> 1, wn = warp & 1;
    int g = lane >> 2, tig = lane & 3;

#pragma unroll
    for (int s = 0; s < 4; s++) {
        int ch = tid + s * 256;
        int r = ch >> 3, k8 = (ch & 7) * 8;
        *reinterpret_cast<uint4*>(&As[r][k8]) =
            *reinterpret_cast<const uint4*>(&Ab[(size_t)(row0 + r) * SCC + k8]);
        *reinterpret_cast<uint4*>(&Bs[r][k8]) =
            *reinterpret_cast<const uint4*>(&Wt2[(size_t)(col0 + r) * SCC + k8]);
    }
    __syncthreads();

    float acc[2][8][4];
#pragma unroll
    for (int am = 0; am < 2; am++)
#pragma unroll
        for (int an = 0; an < 8; an++)
#pragma unroll
            for (int d = 0; d < 4; d++) acc[am][an][d] = 0.f;

#pragma unroll
    for (int ks = 0; ks < 64; ks += 16) {
        uint32_t a[2][4], b[8][2];
#pragma unroll
        for (int am = 0; am < 2; am++) {
            int r = wm * 32 + am * 16 + g;
            a[am][0] = *reinterpret_cast<const uint32_t*>(&As[r][ks + tig * 2]);
            a[am][1] = *reinterpret_cast<const uint32_t*>(&As[r + 8][ks + tig * 2]);
            a[am][2] = *reinterpret_cast<const uint32_t*>(&As[r][ks + tig * 2 + 8]);
            a[am][3] = *reinterpret_cast<const uint32_t*>(&As[r + 8][ks + tig * 2 + 8]);
        }
#pragma unroll
        for (int an = 0; an < 8; an++) {
            int n = wn * 64 + an * 8 + g;
            b[an][0] = *reinterpret_cast<const uint32_t*>(&Bs[n][ks + tig * 2]);
            b[an][1] = *reinterpret_cast<const uint32_t*>(&Bs[n][ks + tig * 2 + 8]);
        }
#pragma unroll
        for (int am = 0; am < 2; am++)
#pragma unroll
            for (int an = 0; an < 8; an++)
                mma16816(acc[am][an], a[am], b[an]);
    }

#pragma unroll
    for (int an = 0; an < 8; an++) {
        int c = wn * 64 + an * 8 + tig * 2;
        float bv0 = bias[col0 + c], bv1 = bias[col0 + c + 1];
        float s0 = 0.f, s1 = 0.f, q0 = 0.f, q1 = 0.f;
#pragma unroll
        for (int am = 0; am < 2; am++) {
            int r = row0 + wm * 32 + am * 16 + g;
            float v0 = acc[am][an][0] + bv0, v1 = acc[am][an][1] + bv1;
            float v2 = acc[am][an][2] + bv0, v3 = acc[am][an][3] + bv1;
            float2 w0; w0.x = v0; w0.y = v1;
            float2 w1; w1.x = v2; w1.y = v3;
            *reinterpret_cast<float2*>(&Cb[(size_t)r * OUTC + col0 + c]) = w0;
            *reinterpret_cast<float2*>(&Cb[(size_t)(r + 8) * OUTC + col0 + c]) = w1;
            s0 += v0 + v2; s1 += v1 + v3;
            q0 += v0 * v0 + v2 * v2; q1 += v1 * v1 + v3 * v3;
        }
#pragma unroll
        for (int m = 4; m <= 16; m <<= 1) {
            s0 += __shfl_xor_sync(0xffffffffu, s0, m);
            s1 += __shfl_xor_sync(0xffffffffu, s1, m);
            q0 += __shfl_xor_sync(0xffffffffu, q0, m);
            q1 += __shfl_xor_sync(0xffffffffu, q1, m);
        }
        if (g == 0) {
            s_red[0][wm][c] = s0; s_red[0][wm][c + 1] = s1;
            s_red[1][wm][c] = q0; s_red[1][wm][c + 1] = q1;
        }
    }
    __syncthreads();
    {
        int c = tid & 127, s = tid >> 7;
        float v = s_red[s][0][c] + s_red[s][1][c] + s_red[s][2][c] + s_red[s][3][c];
        part[((size_t)(cl * 2 + s) * 64 + blockIdx.x) * OUTC + col0 + c] = v;
    }
}

// ---------------- batch norm finalize + apply ----------------
__global__ __launch_bounds__(256) void bn_final(const float* __restrict__ part,
                                                float* __restrict__ mu,
                                                float* __restrict__ rstd)
{
    int cl = blockIdx.x, ch = threadIdx.x;
    float s = 0.f, s2 = 0.f;
    for (int r = 0; r < 64; r++) {
        s  += part[((size_t)(cl * 2 + 0) * 64 + r) * OUTC + ch];
        s2 += part[((size_t)(cl * 2 + 1) * 64 + r) * OUTC + ch];
    }
    float m = s * (1.0f / 8192.0f);
    float v = s2 * (1.0f / 8192.0f) - m * m;
    v = v < 0.f ? 0.f : v;
    mu[cl * OUTC + ch]   = m;
    rstd[cl * OUTC + ch] = rsqrtf(v + 1e-5f);
}

__global__ __launch_bounds__(256) void bn_apply(float* __restrict__ y,
                                                const float* __restrict__ mu,
                                                const float* __restrict__ rstd,
                                                const float* __restrict__ gamma,
                                                const float* __restrict__ beta)
{
    size_t i4 = (size_t)blockIdx.x * blockDim.x + threadIdx.x;
    size_t base = i4 * 4;
    int ch = (int)(base & (OUTC - 1));
    int cl = (int)(base >> 21);
    float4 v = *reinterpret_cast<float4*>(&y[base]);
    const float* muc = mu + cl * OUTC + ch;
    const float* rsc = rstd + cl * OUTC + ch;
    const float* gc = gamma + ch;
    const float* bc = beta + ch;
    float t0 = gc[0] * (v.x - muc[0]) * rsc[0] + bc[0];
    float t1 = gc[1] * (v.y - muc[1]) * rsc[1] + bc[1];
    float t2 = gc[2] * (v.z - muc[2]) * rsc[2] + bc[2];
    float t3 = gc[3] * (v.w - muc[3]) * rsc[3] + bc[3];
    v.x = t0 > 0.f ? t0 : 0.1f * t0;
    v.y = t1 > 0.f ? t1 : 0.1f * t1;
    v.z = t2 > 0.f ? t2 : 0.1f * t2;
    v.w = t3 > 0.f ? t3 : 0.1f * t3;
    *reinterpret_cast<float4*>(&y[base]) = v;
}

// ---------------- launch ----------------
extern "C" void kernel_launch(void* const* d_in, const int* in_sizes, int n_in,
                              void* d_out, int out_size)
{
    const float* src    = (const float*)d_in[0];
    const float* tgt    = (const float*)d_in[1];
    const float* src_c  = (const float*)d_in[2];
    const float* tgt_c  = (const float*)d_in[3];
    const float* W_in   = (const float*)d_in[4];
    const float* b_in   = (const float*)d_in[5];
    const float* kpts   = (const float*)d_in[6];
    const float* W_kp   = (const float*)d_in[7];
    const float* W_out  = (const float*)d_in[8];
    const float* b_out  = (const float*)d_in[9];
    const float* gamma  = (const float*)d_in[10];
    const float* beta   = (const float*)d_in[11];
    float* out = (float*)d_out;

    void* p;
    cudaGetSymbolAddress(&p, g_xh);       __half* xhP   = (__half*)p;
    cudaGetSymbolAddress(&p, g_h);        __half* hP    = (__half*)p;
    cudaGetSymbolAddress(&p, g_idx);      int*    idxP  = (int*)p;
    cudaGetSymbolAddress(&p, g_cnt);      int*    cntP  = (int*)p;
    cudaGetSymbolAddress(&p, g_agg);      __half* aggP  = (__half*)p;
    cudaGetSymbolAddress(&p, g_wt1);      __half* wt1P  = (__half*)p;
    cudaGetSymbolAddress(&p, g_wt);       __half* wtP   = (__half*)p;
    cudaGetSymbolAddress(&p, g_wt2);      __half* wt2P  = (__half*)p;
    cudaGetSymbolAddress(&p, g_h2);       __half* h2P   = (__half*)p;
    cudaGetSymbolAddress(&p, g_part);     float*  partP = (float*)p;
    cudaGetSymbolAddress(&p, g_mu);       float*  muP   = (float*)p;
    cudaGetSymbolAddress(&p, g_rstd);     float*  rstdP = (float*)p;
    cudaGetSymbolAddress(&p, g_cellstart);int*    cstP  = (int*)p;
    cudaGetSymbolAddress(&p, g_sorted);   float4* srtP  = (float4*)p;

    const int KNN_SMEM = KNN_TPB * 33 * 8 + KNN_TPB * 4;   // 34304 B
    cudaFuncSetAttribute(knn_grid, cudaFuncAttributeMaxDynamicSharedMemorySize, KNN_SMEM);

    // 0) grid build + all fp16 conversions (single launch)
    grid_build<<<BUILD_BLOCKS, 512>>>(src_c, tgt_c, src, tgt, W_in, W_kp, W_out,
                                      xhP, wt1P, wtP, wt2P, cstP, srtP);

    // 1) h(fp16) = x @ W_in + b_in  (HMMA)
    gemm_hmma_fh<<<dim3(NP / 128, 2), 256>>>(xhP, wt1P, b_in, hP, INC);

    // 2) grid kNN: sorted order, 4 lanes per query
    knn_grid<<<dim3(NP / KNN_QPB, 2), KNN_TPB, KNN_SMEM>>>(cstP, srtP, idxP, cntP);

    // 3) KPConv aggregation on tensor cores -> agg [N, 960] (fp16)
    agg_mma<<<dim3(NP / 8, 2), 256>>>(src_c, tgt_c, idxP, cntP, hP, kpts, aggP);

    // 4) h2(fp16) = agg @ W_kp  (HMMA)
    gemm_hmma<<<dim3(NP / 128, 2), 256>>>(aggP, wtP, h2P);

    // 5) y = h2 @ W_out + b_out -> d_out (HMMA) with fused BN partials
    gemm_hmma2<<<dim3(NP / 128, 2, 2), 256>>>(h2P, wt2P, b_out, out, partP);

    // 6) batch norm finalize + apply (in place on d_out)
    bn_final<<<2, 256>>>(partP, muP, rstdP);
    bn_apply<<<(2 * NP * OUTC / 4) / 256, 256>>>(out, muP, rstdP, gamma, beta);

    // 7) coords pass-through
    cudaMemcpyAsync(out + (size_t)2 * NP * OUTC, src_c, NP * 3 * sizeof(float),
                    cudaMemcpyDeviceToDevice);
    cudaMemcpyAsync(out + (size_t)2 * NP * OUTC + NP * 3, tgt_c, NP * 3 * sizeof(float),
                    cudaMemcpyDeviceToDevice);
}

// round 16
// speedup vs baseline: 1.1946x; 1.0128x over previous
#include <cuda_runtime.h>
#include <cuda_fp16.h>
#include <stdint.h>
#include <math.h>

#define NP    8192
#define INC   256
#define SCC   64
#define OUTC  256
#define KPN   15
#define KDIM  (KPN * SCC)     // 960
#define KNN_TPB 128           // 32 queries/block x 4 lanes/query
#define KNN_QPB 32

// ---------------- scratch (__device__ globals, no allocations) ----------------
__device__ __align__(256) __half g_xh  [2 * NP * INC];                 // 8 MB fp16 inputs
__device__ __align__(256) __half g_h   [2 * NP * SCC];                 // 2 MB fp16
__device__ __align__(256) int    g_idx [2 * NP * 32];                  // 2 MB
__device__ __align__(256) int    g_cnt [2 * NP];
__device__ __align__(256) __half g_agg [(size_t)2 * NP * KDIM];        // 30 MB (fp16)
__device__ __align__(256) __half g_wt1 [SCC * INC];                    // W_in^T fp16 [64][256]
__device__ __align__(256) __half g_wt  [SCC * KDIM];                   // W_kp^T fp16 [64][960]
__device__ __align__(256) __half g_wt2 [OUTC * SCC];                   // W_out^T fp16 [256][64]
__device__ __align__(256) __half g_h2  [2 * NP * SCC];                 // 2 MB fp16
__device__ __align__(256) float  g_part[2 * 2 * 64 * OUTC];
__device__ __align__(256) float  g_mu  [2 * OUTC];
__device__ __align__(256) float  g_rstd[2 * OUTC];
__device__ __align__(256) int    g_cellstart[2 * 513];
__device__ __align__(256) float4 g_sorted   [2 * NP];   // xyz + original index (bits)

// ---------------- combined grid build + fp16 conversions (one launch) ----------------
__device__ __forceinline__ int cell_of(float x, float y, float z) {
    int cx = (int)(x * 8.0f); cx = cx < 0 ? 0 : (cx > 7 ? 7 : cx);
    int cy = (int)(y * 8.0f); cy = cy < 0 ? 0 : (cy > 7 ? 7 : cy);
    int cz = (int)(z * 8.0f); cz = cz < 0 ? 0 : (cz > 7 ? 7 : cz);
    return (cz * 8 + cy) * 8 + cx;
}

#define BUILD_BLOCKS 66

__global__ __launch_bounds__(512) void grid_build(
    const float* __restrict__ c0, const float* __restrict__ c1,
    const float* __restrict__ src, const float* __restrict__ tgt,
    const float* __restrict__ Win, const float* __restrict__ Wkp,
    const float* __restrict__ Wout,
    __half* __restrict__ xh, __half* __restrict__ wt1,
    __half* __restrict__ wt, __half* __restrict__ wt2,
    int* __restrict__ start, float4* __restrict__ sorted)
{
    int b = blockIdx.x;
    int t = threadIdx.x;
    if (b < 2) {
        __shared__ short s_cell[NP];    // 16 KB
        __shared__ int s_cnt[512], s_sc[512], s_fill[512];
        const float* c = b ? c1 : c0;
        s_cnt[t] = 0; s_fill[t] = 0;
        __syncthreads();
#pragma unroll
        for (int i = 0; i < 16; i++) {
            int p = t + i * 512;
            int cell = cell_of(c[3 * p], c[3 * p + 1], c[3 * p + 2]);
            s_cell[p] = (short)cell;
            atomicAdd(&s_cnt[cell], 1);
        }
        __syncthreads();
        s_sc[t] = s_cnt[t];
        __syncthreads();
#pragma unroll
        for (int off = 1; off < 512; off <<= 1) {
            int v = (t >= off) ? s_sc[t - off] : 0;
            __syncthreads();
            s_sc[t] += v;
            __syncthreads();
        }
        start[b * 513 + t + 1] = s_sc[t];
        if (t == 0) start[b * 513] = 0;
        __syncthreads();
#pragma unroll
        for (int i = 0; i < 16; i++) {
            int p = t + i * 512;
            int cell = s_cell[p];
            int pos = s_sc[cell] - s_cnt[cell] + atomicAdd(&s_fill[cell], 1);
            sorted[b * NP + pos] = make_float4(c[3 * p], c[3 * p + 1], c[3 * p + 2],
                                               __int_as_float(p));
        }
    } else {
        int gt = (b - 2) * 512 + t;
        int stride = (BUILD_BLOCKS - 2) * 512;
        for (int i4 = gt; i4 < (2 * NP * INC) / 4; i4 += stride) {
            size_t base = (size_t)i4 * 4;
            int cl = (int)(base >> 21);
            size_t off = base & ((size_t)NP * INC - 1);
            float4 v = *reinterpret_cast<const float4*>(&(cl ? tgt : src)[off]);
            __half2 h01 = __floats2half2_rn(v.x, v.y);
            __half2 h23 = __floats2half2_rn(v.z, v.w);
            uint2 pk;
            pk.x = *reinterpret_cast<unsigned int*>(&h01);
            pk.y = *reinterpret_cast<unsigned int*>(&h23);
            *reinterpret_cast<uint2*>(&xh[base]) = pk;
        }
        for (int i = gt; i < INC * SCC; i += stride) {
            int k = i >> 6, n = i & 63;
            wt1[n * INC + k] = __float2half_rn(Win[i]);
        }
        for (int i = gt; i < KDIM * SCC; i += stride) {
            int k = i >> 6, n = i & 63;
            wt[n * KDIM + k] = __float2half_rn(Wkp[i]);
        }
        for (int i = gt; i < SCC * OUTC; i += stride) {
            int k = i >> 8, n = i & 255;
            wt2[n * SCC + k] = __float2half_rn(Wout[i]);
        }
    }
}

// ---------------- HMMA helpers ----------------
__device__ __forceinline__ void mma16816(float* c, const uint32_t* a, const uint32_t* b) {
    asm volatile(
        "mma.sync.aligned.m16n8k16.row.col.f32.f16.f16.f32 "
        "{%0,%1,%2,%3}, {%4,%5,%6,%7}, {%8,%9}, {%0,%1,%2,%3};\n"
        : "+f"(c[0]), "+f"(c[1]), "+f"(c[2]), "+f"(c[3])
        : "r"(a[0]), "r"(a[1]), "r"(a[2]), "r"(a[3]), "r"(b[0]), "r"(b[1]));
}

__device__ __forceinline__ void ldmatrix_x4_trans(uint32_t* r, const void* smem_ptr) {
    uint32_t addr = (uint32_t)__cvta_generic_to_shared(smem_ptr);
    asm volatile(
        "ldmatrix.sync.aligned.m8n8.x4.trans.shared.b16 {%0,%1,%2,%3}, [%4];\n"
        : "=r"(r[0]), "=r"(r[1]), "=r"(r[2]), "=r"(r[3]) : "r"(addr));
}

// ---------------- HMMA GEMM (fp16 out + bias): h = A[8192,K] @ Wt^T + b ----------------
__global__ __launch_bounds__(256) void gemm_hmma_fh(
    const __half* __restrict__ A, const __half* __restrict__ Wt,
    const float* __restrict__ bias, __half* __restrict__ C, int K)
{
    __shared__ __half As[128][40];
    __shared__ __half Bs[64][40];

    int cl = blockIdx.y;
    const __half* Ab = A + (size_t)cl * NP * K;
    __half* Cb = C + (size_t)cl * NP * SCC;
    int row0 = blockIdx.x * 128;
    int tid = threadIdx.x, lane = tid & 31, warp = tid >> 5;
    int wm = warp >> 1, wn = warp & 1;
    int g = lane >> 2, tig = lane & 3;

    float acc[2][4][4];
#pragma unroll
    for (int am = 0; am < 2; am++)
#pragma unroll
        for (int an = 0; an < 4; an++)
#pragma unroll
            for (int d = 0; d < 4; d++) acc[am][an][d] = 0.f;

    for (int k0 = 0; k0 < K; k0 += 32) {
#pragma unroll
        for (int s = 0; s < 2; s++) {
            int ch = tid + s * 256;
            int r = ch >> 2, k8 = (ch & 3) * 8;
            *reinterpret_cast<uint4*>(&As[r][k8]) =
                *reinterpret_cast<const uint4*>(&Ab[(size_t)(row0 + r) * K + k0 + k8]);
        }
        {
            int n = tid >> 2, k8 = (tid & 3) * 8;
            *reinterpret_cast<uint4*>(&Bs[n][k8]) =
                *reinterpret_cast<const uint4*>(&Wt[(size_t)n * K + k0 + k8]);
        }
        __syncthreads();

#pragma unroll
        for (int ks = 0; ks < 32; ks += 16) {
            uint32_t a[2][4], b[4][2];
#pragma unroll
            for (int am = 0; am < 2; am++) {
                int r = wm * 32 + am * 16 + g;
                a[am][0] = *reinterpret_cast<const uint32_t*>(&As[r][ks + tig * 2]);
                a[am][1] = *reinterpret_cast<const uint32_t*>(&As[r + 8][ks + tig * 2]);
                a[am][2] = *reinterpret_cast<const uint32_t*>(&As[r][ks + tig * 2 + 8]);
                a[am][3] = *reinterpret_cast<const uint32_t*>(&As[r + 8][ks + tig * 2 + 8]);
            }
#pragma unroll
            for (int an = 0; an < 4; an++) {
                int n = wn * 32 + an * 8 + g;
                b[an][0] = *reinterpret_cast<const uint32_t*>(&Bs[n][ks + tig * 2]);
                b[an][1] = *reinterpret_cast<const uint32_t*>(&Bs[n][ks + tig * 2 + 8]);
            }
#pragma unroll
            for (int am = 0; am < 2; am++)
#pragma unroll
                for (int an = 0; an < 4; an++)
                    mma16816(acc[am][an], a[am], b[an]);
        }
        __syncthreads();
    }

#pragma unroll
    for (int am = 0; am < 2; am++)
#pragma unroll
        for (int an = 0; an < 4; an++) {
            int r = row0 + wm * 32 + am * 16 + g;
            int c = wn * 32 + an * 8 + tig * 2;
            float bv0 = bias[c], bv1 = bias[c + 1];
            __half2 v0 = __floats2half2_rn(acc[am][an][0] + bv0, acc[am][an][1] + bv1);
            __half2 v1 = __floats2half2_rn(acc[am][an][2] + bv0, acc[am][an][3] + bv1);
            *reinterpret_cast<__half2*>(&Cb[(size_t)r * SCC + c]) = v0;
            *reinterpret_cast<__half2*>(&Cb[(size_t)(r + 8) * SCC + c]) = v1;
        }
}

// ---------------- kNN: sorted order, 4 lanes per query (measured) ----------------
__global__ __launch_bounds__(KNN_TPB) void knn_grid(
    const int* __restrict__ start, const float4* __restrict__ sorted,
    int* __restrict__ out_idx, int* __restrict__ out_cnt)
{
    extern __shared__ char smraw[];
    float* smd = (float*)smraw;                          // [128][33]
    int*   smi = (int*)(smraw + KNN_TPB * 33 * 4);       // [128][33]
    int*   s_keep = (int*)(smraw + KNN_TPB * 33 * 8);    // [128]

    int cl = blockIdx.y;
    int tid = threadIdx.x;
    int lq = tid & 3;
    int quad = tid >> 2;
    int s = blockIdx.x * KNN_QPB + quad;

    const int* st = start + cl * 513;
    const float4* srt = sorted + (size_t)cl * NP;

    float4 q4 = srt[s];
    float qx = q4.x, qy = q4.y, qz = q4.z;
    int orig = __float_as_int(q4.w);
    const float R2 = 0.0144f;

    int cx = (int)(qx * 8.0f); cx = cx < 0 ? 0 : (cx > 7 ? 7 : cx);
    int cy = (int)(qy * 8.0f); cy = cy < 0 ? 0 : (cy > 7 ? 7 : cy);
    int cz = (int)(qz * 8.0f); cz = cz < 0 ? 0 : (cz > 7 ? 7 : cz);
    int xlo = cx > 0 ? cx - 1 : 0, xhi = cx < 7 ? cx + 1 : 7;
    int ylo = cy > 0 ? cy - 1 : 0, yhi = cy < 7 ? cy + 1 : 7;
    int zlo = cz > 0 ? cz - 1 : 0, zhi = cz < 7 ? cz + 1 : 7;

    float* md = smd + tid * 33;
    int*   mi = smi + tid * 33;
    int keep = 0;
    float cm = 0.f; int ca = 0;

    for (int z = zlo; z <= zhi; z++)
        for (int y = ylo; y <= yhi; y++) {
            int rowcell = (z * 8 + y) * 8;
            int jb = st[rowcell + xlo];
            int je = st[rowcell + xhi + 1];
#pragma unroll 2
            for (int j = jb + lq; j < je; j += 4) {
                float4 pc = srt[j];
                float dx = __fsub_rn(qx, pc.x);
                float dy = __fsub_rn(qy, pc.y);
                float dz = __fsub_rn(qz, pc.z);
                float d2 = __fadd_rn(__fadd_rn(__fmul_rn(dx, dx), __fmul_rn(dy, dy)),
                                     __fmul_rn(dz, dz));
                if (d2 <= R2) {
                    if (keep < 32) {
                        md[keep] = d2; mi[keep] = __float_as_int(pc.w); keep++;
                        if (keep == 32) {
                            cm = md[0]; ca = 0;
#pragma unroll
                            for (int u = 1; u < 32; u++) { float v = md[u]; if (v > cm) { cm = v; ca = u; } }
                        }
                    } else if (d2 < cm) {
                        md[ca] = d2; mi[ca] = __float_as_int(pc.w);
                        cm = md[0]; ca = 0;
#pragma unroll
                        for (int u = 1; u < 32; u++) { float v = md[u]; if (v > cm) { cm = v; ca = u; } }
                    }
                }
            }
        }

    s_keep[tid] = keep;
    __syncwarp();

    if (lq == 0) {
        for (int l = 1; l < 4; l++) {
            const float* od = smd + (tid + l) * 33;
            const int*   oi2 = smi + (tid + l) * 33;
            int oc = s_keep[tid + l];
            for (int e = 0; e < oc; e++) {
                float d2 = od[e];
                int ix = oi2[e];
                if (keep < 32) {
                    md[keep] = d2; mi[keep] = ix; keep++;
                    if (keep == 32) {
                        cm = md[0]; ca = 0;
#pragma unroll
                        for (int u = 1; u < 32; u++) { float v = md[u]; if (v > cm) { cm = v; ca = u; } }
                    }
                } else if (d2 < cm) {
                    md[ca] = d2; mi[ca] = ix;
                    cm = md[0]; ca = 0;
#pragma unroll
                    for (int u = 1; u < 32; u++) { float v = md[u]; if (v > cm) { cm = v; ca = u; } }
                }
            }
        }
        int* oi = out_idx + ((size_t)cl * NP + orig) * 32;
        for (int u = 0; u < 32; u++) oi[u] = (u < keep) ? mi[u] : 0;
        out_cnt[cl * NP + orig] = keep;
    }
}

// ---------------- KPConv aggregate on TENSOR CORES (B via ldmatrix.trans) ----------------
// Per point: D[16(kp,pad)][64(ch)] = infl[16][32(nb)] @ nb_feats[32][64].
__global__ __launch_bounds__(256) void agg_mma(
    const float* __restrict__ c0, const float* __restrict__ c1,
    const int* __restrict__ idx, const int* __restrict__ cntArr,
    const __half* __restrict__ h, const float* __restrict__ kpts,
    __half* __restrict__ agg)
{
    __shared__ __half s_nb[8][32][72];     // 36864 B  (B tile, 144B row pitch)
    __shared__ __half s_infl[8][16][40];   // 10240 B  (A tile)
    __shared__ float s_kp[45];

    int tid = threadIdx.x, lane = tid & 31, w = tid >> 5;
    int cl = blockIdx.y;
    int pt = blockIdx.x * 8 + w;
    size_t q = (size_t)cl * NP + pt;
    const float* coords = cl ? c1 : c0;

    if (tid < 45) s_kp[tid] = kpts[tid];
    __syncthreads();

    // lane k owns neighbor k: rel + influences
    int j = idx[q * 32 + lane];
    int cnt = cntArr[q];
    float rx = __fsub_rn(coords[3 * j],     coords[3 * pt]);
    float ry = __fsub_rn(coords[3 * j + 1], coords[3 * pt + 1]);
    float rz = __fsub_rn(coords[3 * j + 2], coords[3 * pt + 2]);
    bool valid = lane < cnt;
#pragma unroll
    for (int p = 0; p < KPN; p++) {
        float dx = rx - s_kp[p * 3 + 0];
        float dy = ry - s_kp[p * 3 + 1];
        float dz = rz - s_kp[p * 3 + 2];
        float dist = sqrtf(dx * dx + dy * dy + dz * dz);
        float wgt = fmaxf(1.0f - dist * (1.0f / 0.096f), 0.0f);
        s_infl[w][p][lane] = __float2half_rn(valid ? wgt : 0.0f);
    }
    s_infl[w][15][lane] = __float2half_rn(0.0f);

    // gather 32 neighbor feature rows (64 halves each)
    const __half* hcl = h + (size_t)cl * NP * SCC;
    int r4 = lane >> 3, c8 = lane & 7;
#pragma unroll
    for (int i = 0; i < 8; i++) {
        int r = i * 4 + r4;
        int jr = __shfl_sync(0xffffffffu, j, r);
        uint4 v = *reinterpret_cast<const uint4*>(&hcl[(size_t)jr * SCC + c8 * 8]);
        *reinterpret_cast<uint4*>(&s_nb[w][r][c8 * 8]) = v;
    }
    __syncwarp();

    int g = lane >> 2, tig = lane & 3;
    float acc[8][4];
#pragma unroll
    for (int an = 0; an < 8; an++)
#pragma unroll
        for (int d = 0; d < 4; d++) acc[an][d] = 0.f;

    // ldmatrix lane addressing: tile t = lane>>3, row r = lane&7
    int lt = lane >> 3, lr = lane & 7;

#pragma unroll
    for (int ks = 0; ks < 32; ks += 16) {
        uint32_t a[4];
        a[0] = *reinterpret_cast<const uint32_t*>(&s_infl[w][g][ks + tig * 2]);
        a[1] = *reinterpret_cast<const uint32_t*>(&s_infl[w][g + 8][ks + tig * 2]);
        a[2] = *reinterpret_cast<const uint32_t*>(&s_infl[w][g][ks + tig * 2 + 8]);
        a[3] = *reinterpret_cast<const uint32_t*>(&s_infl[w][g + 8][ks + tig * 2 + 8]);
#pragma unroll
        for (int nn = 0; nn < 4; nn++) {
            // tiles: 0 -> (ks, n0), 1 -> (ks+8, n0), 2 -> (ks, n0+8), 3 -> (ks+8, n0+8)
            int krow = ks + (lt & 1) * 8 + lr;
            int ncol = nn * 16 + (lt >> 1) * 8;
            uint32_t br[4];
            ldmatrix_x4_trans(br, &s_nb[w][krow][ncol]);
            mma16816(acc[nn * 2 + 0], a, &br[0]);
            mma16816(acc[nn * 2 + 1], a, &br[2]);
        }
    }

    // epilogue: D rows g (p=g) and g+8 (p=g+8, skip p=15 pad)
    __half* o = agg + q * KDIM;
#pragma unroll
    for (int an = 0; an < 8; an++) {
        int c = an * 8 + tig * 2;
        __half2 v0 = __floats2half2_rn(acc[an][0], acc[an][1]);
        *reinterpret_cast<__half2*>(&o[g * SCC + c]) = v0;
        if (g < 7) {
            __half2 v1 = __floats2half2_rn(acc[an][2], acc[an][3]);
            *reinterpret_cast<__half2*>(&o[(g + 8) * SCC + c]) = v1;
        }
    }
}

// ---------------- HMMA GEMM 1: h2(fp16) = agg[8192,960] @ Wkp[960,64] ----------------
__global__ __launch_bounds__(256) void gemm_hmma(
    const __half* __restrict__ A, const __half* __restrict__ Wt,
    __half* __restrict__ C)
{
    __shared__ __half As[128][40];
    __shared__ __half Bs[64][40];

    int cl = blockIdx.y;
    const __half* Ab = A + (size_t)cl * NP * KDIM;
    __half* Cb = C + (size_t)cl * NP * SCC;
    int row0 = blockIdx.x * 128;
    int tid = threadIdx.x, lane = tid & 31, warp = tid >> 5;
    int wm = warp >> 1, wn = warp & 1;
    int g = lane >> 2, tig = lane & 3;

    float acc[2][4][4];
#pragma unroll
    for (int am = 0; am < 2; am++)
#pragma unroll
        for (int an = 0; an < 4; an++)
#pragma unroll
            for (int d = 0; d < 4; d++) acc[am][an][d] = 0.f;

    for (int k0 = 0; k0 < KDIM; k0 += 32) {
#pragma unroll
        for (int s = 0; s < 2; s++) {
            int ch = tid + s * 256;
            int r = ch >> 2, k8 = (ch & 3) * 8;
            *reinterpret_cast<uint4*>(&As[r][k8]) =
                *reinterpret_cast<const uint4*>(&Ab[(size_t)(row0 + r) * KDIM + k0 + k8]);
        }
        {
            int n = tid >> 2, k8 = (tid & 3) * 8;
            *reinterpret_cast<uint4*>(&Bs[n][k8]) =
                *reinterpret_cast<const uint4*>(&Wt[(size_t)n * KDIM + k0 + k8]);
        }
        __syncthreads();

#pragma unroll
        for (int ks = 0; ks < 32; ks += 16) {
            uint32_t a[2][4], b[4][2];
#pragma unroll
            for (int am = 0; am < 2; am++) {
                int r = wm * 32 + am * 16 + g;
                a[am][0] = *reinterpret_cast<const uint32_t*>(&As[r][ks + tig * 2]);
                a[am][1] = *reinterpret_cast<const uint32_t*>(&As[r + 8][ks + tig * 2]);
                a[am][2] = *reinterpret_cast<const uint32_t*>(&As[r][ks + tig * 2 + 8]);
                a[am][3] = *reinterpret_cast<const uint32_t*>(&As[r + 8][ks + tig * 2 + 8]);
            }
#pragma unroll
            for (int an = 0; an < 4; an++) {
                int n = wn * 32 + an * 8 + g;
                b[an][0] = *reinterpret_cast<const uint32_t*>(&Bs[n][ks + tig * 2]);
                b[an][1] = *reinterpret_cast<const uint32_t*>(&Bs[n][ks + tig * 2 + 8]);
            }
#pragma unroll
            for (int am = 0; am < 2; am++)
#pragma unroll
                for (int an = 0; an < 4; an++)
                    mma16816(acc[am][an], a[am], b[an]);
        }
        __syncthreads();
    }

#pragma unroll
    for (int am = 0; am < 2; am++)
#pragma unroll
        for (int an = 0; an < 4; an++) {
            int r = row0 + wm * 32 + am * 16 + g;
            int c = wn * 32 + an * 8 + tig * 2;
            __half2 v0 = __floats2half2_rn(acc[am][an][0], acc[am][an][1]);
            __half2 v1 = __floats2half2_rn(acc[am][an][2], acc[am][an][3]);
            *reinterpret_cast<__half2*>(&Cb[(size_t)r * SCC + c]) = v0;
            *reinterpret_cast<__half2*>(&Cb[(size_t)(r + 8) * SCC + c]) = v1;
        }
}

// ---------------- HMMA GEMM 2: y = h2[8192,64] @ W_out[64,256] + b + BN partials ----------------
__global__ __launch_bounds__(256) void gemm_hmma2(
    const __half* __restrict__ A, const __half* __restrict__ Wt2,
    const float* __restrict__ bias, float* __restrict__ C,
    float* __restrict__ part)
{
    __shared__ __half As[128][72];
    __shared__ __half Bs[128][72];
    __shared__ float s_red[2][4][128];

    int cl = blockIdx.z;
    const __half* Ab = A + (size_t)cl * NP * SCC;
    float* Cb = C + (size_t)cl * NP * OUTC;
    int row0 = blockIdx.x * 128;
    int col0 = blockIdx.y * 128;
    int tid = threadIdx.x, lane = tid & 31, warp = tid >> 5;
    int wm = warp >> 1, wn = warp & 1;
    int g = lane >> 2, tig = lane & 3;

#pragma unroll
    for (int s = 0; s < 4; s++) {
        int ch = tid + s * 256;
        int r = ch >> 3, k8 = (ch & 7) * 8;
        *reinterpret_cast<uint4*>(&As[r][k8]) =
            *reinterpret_cast<const uint4*>(&Ab[(size_t)(row0 + r) * SCC + k8]);
        *reinterpret_cast<uint4*>(&Bs[r][k8]) =
            *reinterpret_cast<const uint4*>(&Wt2[(size_t)(col0 + r) * SCC + k8]);
    }
    __syncthreads();

    float acc[2][8][4];
#pragma unroll
    for (int am = 0; am < 2; am++)
#pragma unroll
        for (int an = 0; an < 8; an++)
#pragma unroll
            for (int d = 0; d < 4; d++) acc[am][an][d] = 0.f;

#pragma unroll
    for (int ks = 0; ks < 64; ks += 16) {
        uint32_t a[2][4], b[8][2];
#pragma unroll
        for (int am = 0; am < 2; am++) {
            int r = wm * 32 + am * 16 + g;
            a[am][0] = *reinterpret_cast<const uint32_t*>(&As[r][ks + tig * 2]);
            a[am][1] = *reinterpret_cast<const uint32_t*>(&As[r + 8][ks + tig * 2]);
            a[am][2] = *reinterpret_cast<const uint32_t*>(&As[r][ks + tig * 2 + 8]);
            a[am][3] = *reinterpret_cast<const uint32_t*>(&As[r + 8][ks + tig * 2 + 8]);
        }
#pragma unroll
        for (int an = 0; an < 8; an++) {
            int n = wn * 64 + an * 8 + g;
            b[an][0] = *reinterpret_cast<const uint32_t*>(&Bs[n][ks + tig * 2]);
            b[an][1] = *reinterpret_cast<const uint32_t*>(&Bs[n][ks + tig * 2 + 8]);
        }
#pragma unroll
        for (int am = 0; am < 2; am++)
#pragma unroll
            for (int an = 0; an < 8; an++)
                mma16816(acc[am][an], a[am], b[an]);
    }

#pragma unroll
    for (int an = 0; an < 8; an++) {
        int c = wn * 64 + an * 8 + tig * 2;
        float bv0 = bias[col0 + c], bv1 = bias[col0 + c + 1];
        float s0 = 0.f, s1 = 0.f, q0 = 0.f, q1 = 0.f;
#pragma unroll
        for (int am = 0; am < 2; am++) {
            int r = row0 + wm * 32 + am * 16 + g;
            float v0 = acc[am][an][0] + bv0, v1 = acc[am][an][1] + bv1;
            float v2 = acc[am][an][2] + bv0, v3 = acc[am][an][3] + bv1;
            float2 w0; w0.x = v0; w0.y = v1;
            float2 w1; w1.x = v2; w1.y = v3;
            *reinterpret_cast<float2*>(&Cb[(size_t)r * OUTC + col0 + c]) = w0;
            *reinterpret_cast<float2*>(&Cb[(size_t)(r + 8) * OUTC + col0 + c]) = w1;
            s0 += v0 + v2; s1 += v1 + v3;
            q0 += v0 * v0 + v2 * v2; q1 += v1 * v1 + v3 * v3;
        }
#pragma unroll
        for (int m = 4; m <= 16; m <<= 1) {
            s0 += __shfl_xor_sync(0xffffffffu, s0, m);
            s1 += __shfl_xor_sync(0xffffffffu, s1, m);
            q0 += __shfl_xor_sync(0xffffffffu, q0, m);
            q1 += __shfl_xor_sync(0xffffffffu, q1, m);
        }
        if (g == 0) {
            s_red[0][wm][c] = s0; s_red[0][wm][c + 1] = s1;
            s_red[1][wm][c] = q0; s_red[1][wm][c + 1] = q1;
        }
    }
    __syncthreads();
    {
        int c = tid & 127, s = tid >> 7;
        float v = s_red[s][0][c] + s_red[s][1][c] + s_red[s][2][c] + s_red[s][3][c];
        part[((size_t)(cl * 2 + s) * 64 + blockIdx.x) * OUTC + col0 + c] = v;
    }
}

// ---------------- batch norm finalize + apply ----------------
__global__ __launch_bounds__(256) void bn_final(const float* __restrict__ part,
                                                float* __restrict__ mu,
                                                float* __restrict__ rstd)
{
    int cl = blockIdx.x, ch = threadIdx.x;
    float s = 0.f, s2 = 0.f;
    for (int r = 0; r < 64; r++) {
        s  += part[((size_t)(cl * 2 + 0) * 64 + r) * OUTC + ch];
        s2 += part[((size_t)(cl * 2 + 1) * 64 + r) * OUTC + ch];
    }
    float m = s * (1.0f / 8192.0f);
    float v = s2 * (1.0f / 8192.0f) - m * m;
    v = v < 0.f ? 0.f : v;
    mu[cl * OUTC + ch]   = m;
    rstd[cl * OUTC + ch] = rsqrtf(v + 1e-5f);
}

__global__ __launch_bounds__(256) void bn_apply(float* __restrict__ y,
                                                const float* __restrict__ mu,
                                                const float* __restrict__ rstd,
                                                const float* __restrict__ gamma,
                                                const float* __restrict__ beta)
{
    size_t i4 = (size_t)blockIdx.x * blockDim.x + threadIdx.x;
    size_t base = i4 * 4;
    int ch = (int)(base & (OUTC - 1));
    int cl = (int)(base >> 21);
    float4 v = *reinterpret_cast<float4*>(&y[base]);
    const float* muc = mu + cl * OUTC + ch;
    const float* rsc = rstd + cl * OUTC + ch;
    const float* gc = gamma + ch;
    const float* bc = beta + ch;
    float t0 = gc[0] * (v.x - muc[0]) * rsc[0] + bc[0];
    float t1 = gc[1] * (v.y - muc[1]) * rsc[1] + bc[1];
    float t2 = gc[2] * (v.z - muc[2]) * rsc[2] + bc[2];
    float t3 = gc[3] * (v.w - muc[3]) * rsc[3] + bc[3];
    v.x = t0 > 0.f ? t0 : 0.1f * t0;
    v.y = t1 > 0.f ? t1 : 0.1f * t1;
    v.z = t2 > 0.f ? t2 : 0.1f * t2;
    v.w = t3 > 0.f ? t3 : 0.1f * t3;
    *reinterpret_cast<float4*>(&y[base]) = v;
}

// ---------------- launch ----------------
extern "C" void kernel_launch(void* const* d_in, const int* in_sizes, int n_in,
                              void* d_out, int out_size)
{
    const float* src    = (const float*)d_in[0];
    const float* tgt    = (const float*)d_in[1];
    const float* src_c  = (const float*)d_in[2];
    const float* tgt_c  = (const float*)d_in[3];
    const float* W_in   = (const float*)d_in[4];
    const float* b_in   = (const float*)d_in[5];
    const float* kpts   = (const float*)d_in[6];
    const float* W_kp   = (const float*)d_in[7];
    const float* W_out  = (const float*)d_in[8];
    const float* b_out  = (const float*)d_in[9];
    const float* gamma  = (const float*)d_in[10];
    const float* beta   = (const float*)d_in[11];
    float* out = (float*)d_out;

    void* p;
    cudaGetSymbolAddress(&p, g_xh);       __half* xhP   = (__half*)p;
    cudaGetSymbolAddress(&p, g_h);        __half* hP    = (__half*)p;
    cudaGetSymbolAddress(&p, g_idx);      int*    idxP  = (int*)p;
    cudaGetSymbolAddress(&p, g_cnt);      int*    cntP  = (int*)p;
    cudaGetSymbolAddress(&p, g_agg);      __half* aggP  = (__half*)p;
    cudaGetSymbolAddress(&p, g_wt1);      __half* wt1P  = (__half*)p;
    cudaGetSymbolAddress(&p, g_wt);       __half* wtP   = (__half*)p;
    cudaGetSymbolAddress(&p, g_wt2);      __half* wt2P  = (__half*)p;
    cudaGetSymbolAddress(&p, g_h2);       __half* h2P   = (__half*)p;
    cudaGetSymbolAddress(&p, g_part);     float*  partP = (float*)p;
    cudaGetSymbolAddress(&p, g_mu);       float*  muP   = (float*)p;
    cudaGetSymbolAddress(&p, g_rstd);     float*  rstdP = (float*)p;
    cudaGetSymbolAddress(&p, g_cellstart);int*    cstP  = (int*)p;
    cudaGetSymbolAddress(&p, g_sorted);   float4* srtP  = (float4*)p;

    const int KNN_SMEM = KNN_TPB * 33 * 8 + KNN_TPB * 4;   // 34304 B
    cudaFuncSetAttribute(knn_grid, cudaFuncAttributeMaxDynamicSharedMemorySize, KNN_SMEM);

    // 0) grid build + all fp16 conversions (single launch)
    grid_build<<<BUILD_BLOCKS, 512>>>(src_c, tgt_c, src, tgt, W_in, W_kp, W_out,
                                      xhP, wt1P, wtP, wt2P, cstP, srtP);

    // 1) h(fp16) = x @ W_in + b_in  (HMMA)
    gemm_hmma_fh<<<dim3(NP / 128, 2), 256>>>(xhP, wt1P, b_in, hP, INC);

    // 2) grid kNN: sorted order, 4 lanes per query
    knn_grid<<<dim3(NP / KNN_QPB, 2), KNN_TPB, KNN_SMEM>>>(cstP, srtP, idxP, cntP);

    // 3) KPConv aggregation on tensor cores -> agg [N, 960] (fp16)
    agg_mma<<<dim3(NP / 8, 2), 256>>>(src_c, tgt_c, idxP, cntP, hP, kpts, aggP);

    // 4) h2(fp16) = agg @ W_kp  (HMMA)
    gemm_hmma<<<dim3(NP / 128, 2), 256>>>(aggP, wtP, h2P);

    // 5) y = h2 @ W_out + b_out -> d_out (HMMA) with fused BN partials
    gemm_hmma2<<<dim3(NP / 128, 2, 2), 256>>>(h2P, wt2P, b_out, out, partP);

    // 6) batch norm finalize + apply (in place on d_out)
    bn_final<<<2, 256>>>(partP, muP, rstdP);
    bn_apply<<<(2 * NP * OUTC / 4) / 256, 256>>>(out, muP, rstdP, gamma, beta);

    // 7) coords pass-through
    cudaMemcpyAsync(out + (size_t)2 * NP * OUTC, src_c, NP * 3 * sizeof(float),
                    cudaMemcpyDeviceToDevice);
    cudaMemcpyAsync(out + (size_t)2 * NP * OUTC + NP * 3, tgt_c, NP * 3 * sizeof(float),
                    cudaMemcpyDeviceToDevice);
}